// round 3
// baseline (speedup 1.0000x reference)
#include <cuda_runtime.h>

#define NB 8
#define NT 2048
#define NE 128
#define NH 16

// Q/K/V scratch (allocation-free: __device__ globals)
__device__ float g_Q[NB * NT * NH];
__device__ float g_K[NB * NT * NH];
__device__ float g_V[NB * NT * NH];

typedef unsigned long long u64;

__device__ __forceinline__ float ex2f(float x) {
    float y;
    asm("ex2.approx.ftz.f32 %0, %1;" : "=f"(y) : "f"(x));
    return y;
}
// Blackwell packed fp32x2 ops (2x FFMA throughput; ptxas never auto-fuses these)
__device__ __forceinline__ u64 fma2(u64 a, u64 b, u64 c) {
    u64 d; asm("fma.rn.f32x2 %0, %1, %2, %3;" : "=l"(d) : "l"(a), "l"(b), "l"(c)); return d;
}
__device__ __forceinline__ u64 mul2(u64 a, u64 b) {
    u64 d; asm("mul.rn.f32x2 %0, %1, %2;" : "=l"(d) : "l"(a), "l"(b)); return d;
}
__device__ __forceinline__ u64 add2(u64 a, u64 b) {
    u64 d; asm("add.rn.f32x2 %0, %1, %2;" : "=l"(d) : "l"(a), "l"(b)); return d;
}
__device__ __forceinline__ u64 pack2(float lo, float hi) {
    u64 r; asm("mov.b64 %0, {%1,%2};" : "=l"(r) : "f"(lo), "f"(hi)); return r;
}
__device__ __forceinline__ void unpack2(u64 v, float& lo, float& hi) {
    asm("mov.b64 {%0,%1}, %2;" : "=f"(lo), "=f"(hi) : "l"(v));
}

// ---------------------------------------------------------------------------
// Kernel 1: fused QKV projection (f32x2 packed inner loop).
// CTA = 128 threads, 32 tokens. Thread (tg, og) computes 12 output columns.
// ---------------------------------------------------------------------------
__global__ __launch_bounds__(128, 2) void qkv_kernel(
    const float* __restrict__ x,
    const float* __restrict__ Wq,
    const float* __restrict__ Wk,
    const float* __restrict__ Wv)
{
    __shared__ float4 sX[32 * 33];    // 32 tokens x 132 floats (pad)
    __shared__ float4 sW[128 * 12];   // 128 e-rows x 48 floats
    const int tid  = threadIdx.x;
    const int tok0 = blockIdx.x * 32;

    const float4* xg = reinterpret_cast<const float4*>(x) + (size_t)tok0 * 32;
#pragma unroll
    for (int i = 0; i < 8; i++) {
        int idx = i * 128 + tid;
        sX[(idx >> 5) * 33 + (idx & 31)] = xg[idx];
    }
    const float4* wq4 = reinterpret_cast<const float4*>(Wq);
    const float4* wk4 = reinterpret_cast<const float4*>(Wk);
    const float4* wv4 = reinterpret_cast<const float4*>(Wv);
#pragma unroll
    for (int i = 0; i < 12; i++) {
        int idx = i * 128 + tid;       // 0..1535
        int e = idx / 12, c4 = idx % 12;
        float4 w = (c4 < 4) ? wq4[e * 4 + c4]
                 : (c4 < 8) ? wk4[e * 4 + (c4 - 4)]
                            : wv4[e * 4 + (c4 - 8)];
        sW[e * 12 + c4] = w;
    }
    __syncthreads();

    const int og = tid & 3;
    const int tg = tid >> 2;
    u64 acc[6] = {0ull, 0ull, 0ull, 0ull, 0ull, 0ull};

#pragma unroll 8
    for (int e4 = 0; e4 < 32; e4++) {
        float4 xv = sX[tg * 33 + e4];
        float xs[4] = {xv.x, xv.y, xv.z, xv.w};
#pragma unroll
        for (int u = 0; u < 4; u++) {
            u64 xx = pack2(xs[u], xs[u]);
            const ulonglong2* wp =
                reinterpret_cast<const ulonglong2*>(&sW[(e4 * 4 + u) * 12 + og * 3]);
            ulonglong2 wa = wp[0], wb = wp[1], wc = wp[2];
            acc[0] = fma2(xx, wa.x, acc[0]);
            acc[1] = fma2(xx, wa.y, acc[1]);
            acc[2] = fma2(xx, wb.x, acc[2]);
            acc[3] = fma2(xx, wb.y, acc[3]);
            acc[4] = fma2(xx, wc.x, acc[4]);
            acc[5] = fma2(xx, wc.y, acc[5]);
        }
    }
    float av[12];
#pragma unroll
    for (int i = 0; i < 6; i++) unpack2(acc[i], av[2 * i], av[2 * i + 1]);

    const int tok = tok0 + tg;
#pragma unroll
    for (int k = 0; k < 3; k++) {
        int c0 = og * 12 + k * 4;
        float* base = (c0 < 16) ? g_Q : (c0 < 32) ? g_K : g_V;
        int h0 = c0 & 15;
        float4 o = make_float4(av[k*4+0], av[k*4+1], av[k*4+2], av[k*4+3]);
        *reinterpret_cast<float4*>(base + (size_t)tok * NH + h0) = o;
    }
}

// ---------------------------------------------------------------------------
// Kernel 2: causal flash attention, f32x2 packed, 256 thr/CTA,
// 64 queries x 4-way key split, complementary heavy+light CTA pairing.
// ---------------------------------------------------------------------------
__device__ __forceinline__ void kv_step(
    const ulonglong2* __restrict__ sK2, const ulonglong2* __restrict__ sV2, int j,
    const u64* __restrict__ q, float& m, float& l, u64* __restrict__ a)
{
    ulonglong2 k0 = sK2[j*4+0], k1 = sK2[j*4+1], k2 = sK2[j*4+2], k3 = sK2[j*4+3];
    // two independent packed dot-product chains (q pre-scaled to log2 units)
    u64 c0 = fma2(q[0], k0.x, fma2(q[2], k1.x, fma2(q[4], k2.x, mul2(q[6], k3.x))));
    u64 c1 = fma2(q[1], k0.y, fma2(q[3], k1.y, fma2(q[5], k2.y, mul2(q[7], k3.y))));
    float slo, shi;
    unpack2(add2(c0, c1), slo, shi);
    float s = slo + shi;

    ulonglong2 v0 = sV2[j*4+0], v1 = sV2[j*4+1], v2 = sV2[j*4+2], v3 = sV2[j*4+3];
    if (s > m) {                 // rare: new running max -> rescale accumulators
        float cf = ex2f(m - s);
        m = s;
        l = fmaf(l, cf, 1.f);
        u64 cc = pack2(cf, cf);
        a[0] = fma2(a[0], cc, v0.x); a[1] = fma2(a[1], cc, v0.y);
        a[2] = fma2(a[2], cc, v1.x); a[3] = fma2(a[3], cc, v1.y);
        a[4] = fma2(a[4], cc, v2.x); a[5] = fma2(a[5], cc, v2.y);
        a[6] = fma2(a[6], cc, v3.x); a[7] = fma2(a[7], cc, v3.y);
    } else {                     // common: 1 MUFU + 1 FADD + 8 packed FMA
        float p = ex2f(s - m);
        l += p;
        u64 pp = pack2(p, p);
        a[0] = fma2(pp, v0.x, a[0]); a[1] = fma2(pp, v0.y, a[1]);
        a[2] = fma2(pp, v1.x, a[2]); a[3] = fma2(pp, v1.y, a[3]);
        a[4] = fma2(pp, v2.x, a[4]); a[5] = fma2(pp, v2.y, a[5]);
        a[6] = fma2(pp, v3.x, a[6]); a[7] = fma2(pp, v3.y, a[7]);
    }
}

__global__ __launch_bounds__(256, 2) void attn_kernel(float* __restrict__ out)
{
    __shared__ float4 sKf[512];   // 128 keys x 16 floats
    __shared__ float4 sVf[512];

    // 296 CTAs: classic placement maps bid and bid+148 to the same SM, so pair
    // the i-th heaviest job (desc order) with the i-th lightest -> ~const 17
    // tiles per SM. bids >= 256 are placement dummies.
    const int bid = blockIdx.x;
    if (bid >= 256) return;
    const int j   = (bid < 148) ? bid : (403 - bid);  // desc-sorted job index
    const int qt  = 31 - (j >> 3);                    // 64-query tile
    const int b   = j & 7;

    const int tid = threadIdx.x;
    const int r   = tid & 3;             // 4-way key split
    const int ql  = tid >> 2;            // local query 0..63
    const int qg  = qt * 64 + ql;

    const float4* qp = reinterpret_cast<const float4*>(g_Q + ((size_t)b * NT + qg) * NH);
    const float SC = 0.25f * 1.44269504088896340736f;  // headsize^-.5 * log2(e)
    u64 q[8];
#pragma unroll
    for (int i = 0; i < 4; i++) {
        float4 t = qp[i];
        q[2*i]   = pack2(t.x * SC, t.y * SC);
        q[2*i+1] = pack2(t.z * SC, t.w * SC);
    }

    float m = -1e30f, l = 0.f;
    u64 a[8];
#pragma unroll
    for (int i = 0; i < 8; i++) a[i] = 0ull;

    const int ntiles = (qt >> 1) + 1;
    const float4* Kg = reinterpret_cast<const float4*>(g_K + (size_t)b * NT * NH);
    const float4* Vg = reinterpret_cast<const float4*>(g_V + (size_t)b * NT * NH);
    const ulonglong2* sK2 = reinterpret_cast<const ulonglong2*>(sKf);
    const ulonglong2* sV2 = reinterpret_cast<const ulonglong2*>(sVf);

    for (int kt = 0; kt < ntiles; kt++) {
#pragma unroll
        for (int i = 0; i < 2; i++) {
            int idx = i * 256 + tid;
            sKf[idx] = Kg[kt * 512 + idx];
            sVf[idx] = Vg[kt * 512 + idx];
        }
        __syncthreads();

        int jlim = qg - (kt << 7);
        if (jlim >= 127) {
#pragma unroll 4
            for (int jj = 0; jj < 32; jj++)
                kv_step(sK2, sV2, 4 * jj + r, q, m, l, a);
        } else {
            for (int jk = r; jk <= jlim; jk += 4)
                kv_step(sK2, sV2, jk, q, m, l, a);
        }
        __syncthreads();
    }

    // combine the 4 key-split lanes (tid&3): tree over xor 1, xor 2
    const unsigned FULL = 0xffffffffu;
#pragma unroll
    for (int d = 1; d <= 2; d <<= 1) {
        float m2 = __shfl_xor_sync(FULL, m, d);
        float l2 = __shfl_xor_sync(FULL, l, d);
        float mx = fmaxf(m, m2);
        float cs = ex2f(m - mx);
        float co = ex2f(m2 - mx);
        l = fmaf(l, cs, l2 * co);
        m = mx;
        u64 csp = pack2(cs, cs), cop = pack2(co, co);
#pragma unroll
        for (int i = 0; i < 8; i++) {
            u64 o = __shfl_xor_sync(FULL, a[i], d);
            a[i] = fma2(a[i], csp, mul2(o, cop));
        }
    }

    if (r == 0) {
        float inv = 1.0f / l;
        u64 ip = pack2(inv, inv);
        float oc[16];
#pragma unroll
        for (int i = 0; i < 8; i++) {
            u64 t = mul2(a[i], ip);
            unpack2(t, oc[2*i], oc[2*i+1]);
        }
        float4* op = reinterpret_cast<float4*>(out + ((size_t)b * NT + qg) * NH);
        op[0] = make_float4(oc[0],  oc[1],  oc[2],  oc[3]);
        op[1] = make_float4(oc[4],  oc[5],  oc[6],  oc[7]);
        op[2] = make_float4(oc[8],  oc[9],  oc[10], oc[11]);
        op[3] = make_float4(oc[12], oc[13], oc[14], oc[15]);
    }
}

extern "C" void kernel_launch(void* const* d_in, const int* in_sizes, int n_in,
                              void* d_out, int out_size)
{
    const float* x  = (const float*)d_in[0];
    const float* Wq = (const float*)d_in[1];
    const float* Wk = (const float*)d_in[2];
    const float* Wv = (const float*)d_in[3];
    float* out = (float*)d_out;

    qkv_kernel<<<512, 128>>>(x, Wq, Wk, Wv);   // 16384 tokens / 32 per CTA
    attn_kernel<<<296, 128 * 2>>>(out);        // 256 jobs + 40 placement dummies
}

// round 4
// speedup vs baseline: 1.4392x; 1.4392x over previous
#include <cuda_runtime.h>

#define NB 8
#define NT 2048
#define NE 128
#define NH 16

// Q/K/V scratch (allocation-free: __device__ globals)
__device__ float g_Q[NB * NT * NH];
__device__ float g_K[NB * NT * NH];
__device__ float g_V[NB * NT * NH];

typedef unsigned long long u64;

__device__ __forceinline__ float ex2f(float x) {
    float y;
    asm("ex2.approx.ftz.f32 %0, %1;" : "=f"(y) : "f"(x));
    return y;
}
// Blackwell packed fp32x2 (2x fp32 FMA throughput; ptxas never auto-fuses)
__device__ __forceinline__ u64 fma2(u64 a, u64 b, u64 c) {
    u64 d; asm("fma.rn.f32x2 %0, %1, %2, %3;" : "=l"(d) : "l"(a), "l"(b), "l"(c)); return d;
}
__device__ __forceinline__ u64 mul2(u64 a, u64 b) {
    u64 d; asm("mul.rn.f32x2 %0, %1, %2;" : "=l"(d) : "l"(a), "l"(b)); return d;
}
__device__ __forceinline__ u64 add2(u64 a, u64 b) {
    u64 d; asm("add.rn.f32x2 %0, %1, %2;" : "=l"(d) : "l"(a), "l"(b)); return d;
}
__device__ __forceinline__ u64 pack2(float lo, float hi) {
    u64 r; asm("mov.b64 %0, {%1,%2};" : "=l"(r) : "f"(lo), "f"(hi)); return r;
}
__device__ __forceinline__ void unpack2(u64 v, float& lo, float& hi) {
    asm("mov.b64 {%0,%1}, %2;" : "=f"(lo), "=f"(hi) : "l"(v));
}

// ---------------------------------------------------------------------------
// Kernel 1: fused QKV projection (f32x2 packed inner loop). 32 tokens/CTA.
// ---------------------------------------------------------------------------
__global__ __launch_bounds__(128, 2) void qkv_kernel(
    const float* __restrict__ x,
    const float* __restrict__ Wq,
    const float* __restrict__ Wk,
    const float* __restrict__ Wv)
{
    __shared__ float4 sX[32 * 33];
    __shared__ float4 sW[128 * 12];
    const int tid  = threadIdx.x;
    const int tok0 = blockIdx.x * 32;

    const float4* xg = reinterpret_cast<const float4*>(x) + (size_t)tok0 * 32;
#pragma unroll
    for (int i = 0; i < 8; i++) {
        int idx = i * 128 + tid;
        sX[(idx >> 5) * 33 + (idx & 31)] = xg[idx];
    }
    const float4* wq4 = reinterpret_cast<const float4*>(Wq);
    const float4* wk4 = reinterpret_cast<const float4*>(Wk);
    const float4* wv4 = reinterpret_cast<const float4*>(Wv);
#pragma unroll
    for (int i = 0; i < 12; i++) {
        int idx = i * 128 + tid;
        int e = idx / 12, c4 = idx % 12;
        float4 w = (c4 < 4) ? wq4[e * 4 + c4]
                 : (c4 < 8) ? wk4[e * 4 + (c4 - 4)]
                            : wv4[e * 4 + (c4 - 8)];
        sW[e * 12 + c4] = w;
    }
    __syncthreads();

    const int og = tid & 3;
    const int tg = tid >> 2;
    u64 acc[6] = {0ull, 0ull, 0ull, 0ull, 0ull, 0ull};

#pragma unroll 8
    for (int e4 = 0; e4 < 32; e4++) {
        float4 xv = sX[tg * 33 + e4];
        float xs[4] = {xv.x, xv.y, xv.z, xv.w};
#pragma unroll
        for (int u = 0; u < 4; u++) {
            u64 xx = pack2(xs[u], xs[u]);
            const ulonglong2* wp =
                reinterpret_cast<const ulonglong2*>(&sW[(e4 * 4 + u) * 12 + og * 3]);
            ulonglong2 wa = wp[0], wb = wp[1], wc = wp[2];
            acc[0] = fma2(xx, wa.x, acc[0]);
            acc[1] = fma2(xx, wa.y, acc[1]);
            acc[2] = fma2(xx, wb.x, acc[2]);
            acc[3] = fma2(xx, wb.y, acc[3]);
            acc[4] = fma2(xx, wc.x, acc[4]);
            acc[5] = fma2(xx, wc.y, acc[5]);
        }
    }
    float av[12];
#pragma unroll
    for (int i = 0; i < 6; i++) unpack2(acc[i], av[2 * i], av[2 * i + 1]);

    const int tok = tok0 + tg;
#pragma unroll
    for (int k = 0; k < 3; k++) {
        int c0 = og * 12 + k * 4;
        float* base = (c0 < 16) ? g_Q : (c0 < 32) ? g_K : g_V;
        int h0 = c0 & 15;
        float4 o = make_float4(av[k*4+0], av[k*4+1], av[k*4+2], av[k*4+3]);
        *reinterpret_cast<float4*>(base + (size_t)tok * NH + h0) = o;
    }
}

// ---------------------------------------------------------------------------
// Kernel 2: causal flash attention.
// CTA = 128 thr, 64-query tile. Thread = (slot, r): slot=tid>>2 owns queries
// {qbase+slot, qbase+slot+32} (G=2, K/V row reused), r=tid&3 splits keys 4-way.
// Smem rows padded to 80B (stride 5 float4) -> the 4 r-groups hit disjoint
// bank quads {0-3}/{20-23}/{8-11}/{28-31}: conflict-free.
// ---------------------------------------------------------------------------
__device__ __forceinline__ void upd(
    float s, float& m, float& l, u64* __restrict__ a,
    const ulonglong2& v0, const ulonglong2& v1,
    const ulonglong2& v2, const ulonglong2& v3)
{
    if (s > m) {                 // rare: new running max
        float c = ex2f(m - s);
        m = s;
        l = fmaf(l, c, 1.f);
        u64 cc = pack2(c, c);
        a[0] = fma2(a[0], cc, v0.x); a[1] = fma2(a[1], cc, v0.y);
        a[2] = fma2(a[2], cc, v1.x); a[3] = fma2(a[3], cc, v1.y);
        a[4] = fma2(a[4], cc, v2.x); a[5] = fma2(a[5], cc, v2.y);
        a[6] = fma2(a[6], cc, v3.x); a[7] = fma2(a[7], cc, v3.y);
    } else {                     // common: 1 MUFU + 1 FADD + 8 fma2
        float p = ex2f(s - m);
        l += p;
        u64 pp = pack2(p, p);
        a[0] = fma2(pp, v0.x, a[0]); a[1] = fma2(pp, v0.y, a[1]);
        a[2] = fma2(pp, v1.x, a[2]); a[3] = fma2(pp, v1.y, a[3]);
        a[4] = fma2(pp, v2.x, a[4]); a[5] = fma2(pp, v2.y, a[5]);
        a[6] = fma2(pp, v3.x, a[6]); a[7] = fma2(pp, v3.y, a[7]);
    }
}

__global__ __launch_bounds__(128, 4) void attn_kernel(float* __restrict__ out)
{
    __shared__ float4 sKf[128 * 5];   // 128 key rows, 80B stride
    __shared__ float4 sVf[128 * 5];

    // Complementary pairing: classic placement maps bid and bid+148 to the same
    // SM; pair i-th heaviest with i-th lightest. No dummy CTAs.
    const int bid  = blockIdx.x;
    const int rank = (bid < 148) ? bid : (403 - bid);  // desc-sorted job index
    const int qt   = 31 - (rank >> 3);
    const int b    = rank & 7;

    const int tid  = threadIdx.x;
    const int r    = tid & 3;
    const int slot = tid >> 2;           // 0..31
    const int qg0  = qt * 64 + slot;
    const int qg1  = qg0 + 32;

    const float SC = 0.25f * 1.44269504088896340736f;  // H^-0.5 * log2(e)
    u64 q[16];
    {
        const float4* qp0 = reinterpret_cast<const float4*>(g_Q + ((size_t)b * NT + qg0) * NH);
        const float4* qp1 = reinterpret_cast<const float4*>(g_Q + ((size_t)b * NT + qg1) * NH);
#pragma unroll
        for (int i = 0; i < 4; i++) {
            float4 t0 = qp0[i], t1 = qp1[i];
            q[2*i]     = pack2(t0.x * SC, t0.y * SC);
            q[2*i+1]   = pack2(t0.z * SC, t0.w * SC);
            q[8+2*i]   = pack2(t1.x * SC, t1.y * SC);
            q[8+2*i+1] = pack2(t1.z * SC, t1.w * SC);
        }
    }

    float m0 = -1e30f, l0 = 0.f, m1 = -1e30f, l1 = 0.f;
    u64 a[16];
#pragma unroll
    for (int i = 0; i < 16; i++) a[i] = 0ull;

    const int ntiles = (qt >> 1) + 1;
    const float4* Kg = reinterpret_cast<const float4*>(g_K + (size_t)b * NT * NH);
    const float4* Vg = reinterpret_cast<const float4*>(g_V + (size_t)b * NT * NH);
    const ulonglong2* sK2 = reinterpret_cast<const ulonglong2*>(sKf);
    const ulonglong2* sV2 = reinterpret_cast<const ulonglong2*>(sVf);

    for (int kt = 0; kt < ntiles; kt++) {
#pragma unroll
        for (int i = 0; i < 4; i++) {
            int idx = i * 128 + tid;                  // 0..511 float4
            int dst = (idx >> 2) * 5 + (idx & 3);     // padded row
            sKf[dst] = Kg[kt * 512 + idx];
            sVf[dst] = Vg[kt * 512 + idx];
        }
        __syncthreads();

        if (kt < ntiles - 1) {
            // full tile: 32 keys per thread, both queries unmasked
#pragma unroll 2
            for (int jj = 0; jj < 32; jj++) {
                int j = 4 * jj + r;
                ulonglong2 k0 = sK2[j*5+0], k1 = sK2[j*5+1],
                           k2 = sK2[j*5+2], k3 = sK2[j*5+3];
                u64 c0 = fma2(q[0], k0.x, fma2(q[2], k1.x, fma2(q[4], k2.x, mul2(q[6],  k3.x))));
                u64 c1 = fma2(q[1], k0.y, fma2(q[3], k1.y, fma2(q[5], k2.y, mul2(q[7],  k3.y))));
                u64 d0 = fma2(q[8], k0.x, fma2(q[10],k1.x, fma2(q[12],k2.x, mul2(q[14], k3.x))));
                u64 d1 = fma2(q[9], k0.y, fma2(q[11],k1.y, fma2(q[13],k2.y, mul2(q[15], k3.y))));
                float slo, shi, tlo, thi;
                unpack2(add2(c0, c1), slo, shi);
                unpack2(add2(d0, d1), tlo, thi);
                float s0 = slo + shi, s1 = tlo + thi;
                ulonglong2 v0 = sV2[j*5+0], v1 = sV2[j*5+1],
                           v2 = sV2[j*5+2], v3 = sV2[j*5+3];
                upd(s0, m0, l0, a,     v0, v1, v2, v3);
                upd(s1, m1, l1, a + 8, v0, v1, v2, v3);
            }
        } else {
            // diagonal tile: query0 masked past jlim0, query1 past jlim1
            const int kbase = kt << 7;
            const int jlim0 = qg0 - kbase;
            const int jlim1 = qg1 - kbase;   // = jlim0 + 32
            for (int j = r; j <= jlim1; j += 4) {
                ulonglong2 k0 = sK2[j*5+0], k1 = sK2[j*5+1],
                           k2 = sK2[j*5+2], k3 = sK2[j*5+3];
                u64 c0 = fma2(q[0], k0.x, fma2(q[2], k1.x, fma2(q[4], k2.x, mul2(q[6],  k3.x))));
                u64 c1 = fma2(q[1], k0.y, fma2(q[3], k1.y, fma2(q[5], k2.y, mul2(q[7],  k3.y))));
                u64 d0 = fma2(q[8], k0.x, fma2(q[10],k1.x, fma2(q[12],k2.x, mul2(q[14], k3.x))));
                u64 d1 = fma2(q[9], k0.y, fma2(q[11],k1.y, fma2(q[13],k2.y, mul2(q[15], k3.y))));
                float slo, shi, tlo, thi;
                unpack2(add2(c0, c1), slo, shi);
                unpack2(add2(d0, d1), tlo, thi);
                float s0 = slo + shi, s1 = tlo + thi;
                ulonglong2 v0 = sV2[j*5+0], v1 = sV2[j*5+1],
                           v2 = sV2[j*5+2], v3 = sV2[j*5+3];
                if (j <= jlim0) upd(s0, m0, l0, a, v0, v1, v2, v3);
                upd(s1, m1, l1, a + 8, v0, v1, v2, v3);
            }
        }
        __syncthreads();
    }

    // combine the 4 key-split lanes (tid&3) via xor-1, xor-2 tree
    const unsigned FULL = 0xffffffffu;
#pragma unroll
    for (int d = 1; d <= 2; d <<= 1) {
        float mo0 = __shfl_xor_sync(FULL, m0, d);
        float lo0 = __shfl_xor_sync(FULL, l0, d);
        float mo1 = __shfl_xor_sync(FULL, m1, d);
        float lo1 = __shfl_xor_sync(FULL, l1, d);
        float mx0 = fmaxf(m0, mo0), mx1 = fmaxf(m1, mo1);
        float cs0 = ex2f(m0 - mx0), co0 = ex2f(mo0 - mx0);
        float cs1 = ex2f(m1 - mx1), co1 = ex2f(mo1 - mx1);
        l0 = fmaf(l0, cs0, lo0 * co0);
        l1 = fmaf(l1, cs1, lo1 * co1);
        m0 = mx0; m1 = mx1;
        u64 csp0 = pack2(cs0, cs0), cop0 = pack2(co0, co0);
        u64 csp1 = pack2(cs1, cs1), cop1 = pack2(co1, co1);
#pragma unroll
        for (int i = 0; i < 8; i++) {
            u64 o0 = __shfl_xor_sync(FULL, a[i],     d);
            u64 o1 = __shfl_xor_sync(FULL, a[i + 8], d);
            a[i]     = fma2(a[i],     csp0, mul2(o0, cop0));
            a[i + 8] = fma2(a[i + 8], csp1, mul2(o1, cop1));
        }
    }

    if (r == 0) {
        float inv0 = 1.0f / l0, inv1 = 1.0f / l1;
        u64 ip0 = pack2(inv0, inv0), ip1 = pack2(inv1, inv1);
        float oc[32];
#pragma unroll
        for (int i = 0; i < 8; i++) {
            unpack2(mul2(a[i],     ip0), oc[2*i],      oc[2*i+1]);
            unpack2(mul2(a[i + 8], ip1), oc[16+2*i],   oc[16+2*i+1]);
        }
        float4* op0 = reinterpret_cast<float4*>(out + ((size_t)b * NT + qg0) * NH);
        float4* op1 = reinterpret_cast<float4*>(out + ((size_t)b * NT + qg1) * NH);
#pragma unroll
        for (int i = 0; i < 4; i++) {
            op0[i] = make_float4(oc[4*i], oc[4*i+1], oc[4*i+2], oc[4*i+3]);
            op1[i] = make_float4(oc[16+4*i], oc[16+4*i+1], oc[16+4*i+2], oc[16+4*i+3]);
        }
    }
}

extern "C" void kernel_launch(void* const* d_in, const int* in_sizes, int n_in,
                              void* d_out, int out_size)
{
    const float* x  = (const float*)d_in[0];
    const float* Wq = (const float*)d_in[1];
    const float* Wk = (const float*)d_in[2];
    const float* Wv = (const float*)d_in[3];
    float* out = (float*)d_out;

    qkv_kernel<<<512, 128>>>(x, Wq, Wk, Wv);   // 16384 tokens / 32 per CTA
    attn_kernel<<<256, 128>>>(out);            // 8 batches x 32 q-tiles
}

// round 5
// speedup vs baseline: 2.4035x; 1.6700x over previous
#include <cuda_runtime.h>

#define NB 8
#define NT 2048
#define NE 128
#define NH 16

// Q/K/V scratch + split-K partials (allocation-free: __device__ globals)
__device__ float g_Q[NB * NT * NH];
__device__ float g_K[NB * NT * NH];
__device__ float g_V[NB * NT * NH];
// partial flash state per (job=b*32*4+qt*4+kc, query): m, l, a[16]
__device__ float g_pm[8 * 32 * 4 * 64];
__device__ float g_pl[8 * 32 * 4 * 64];
__device__ float g_pa[8 * 32 * 4 * 64 * 16];

typedef unsigned long long u64;

__device__ __forceinline__ float ex2f(float x) {
    float y;
    asm("ex2.approx.ftz.f32 %0, %1;" : "=f"(y) : "f"(x));
    return y;
}
// Blackwell packed fp32x2 (2x fp32 FMA throughput; ptxas never auto-fuses)
__device__ __forceinline__ u64 fma2(u64 a, u64 b, u64 c) {
    u64 d; asm("fma.rn.f32x2 %0, %1, %2, %3;" : "=l"(d) : "l"(a), "l"(b), "l"(c)); return d;
}
__device__ __forceinline__ u64 mul2(u64 a, u64 b) {
    u64 d; asm("mul.rn.f32x2 %0, %1, %2;" : "=l"(d) : "l"(a), "l"(b)); return d;
}
__device__ __forceinline__ u64 add2(u64 a, u64 b) {
    u64 d; asm("add.rn.f32x2 %0, %1, %2;" : "=l"(d) : "l"(a), "l"(b)); return d;
}
__device__ __forceinline__ u64 pack2(float lo, float hi) {
    u64 r; asm("mov.b64 %0, {%1,%2};" : "=l"(r) : "f"(lo), "f"(hi)); return r;
}
__device__ __forceinline__ void unpack2(u64 v, float& lo, float& hi) {
    asm("mov.b64 {%0,%1}, %2;" : "=f"(lo), "=f"(hi) : "l"(v));
}

// ---------------------------------------------------------------------------
// Kernel 1: fused QKV projection (f32x2 packed inner loop). 32 tokens/CTA.
// ---------------------------------------------------------------------------
__global__ __launch_bounds__(128, 2) void qkv_kernel(
    const float* __restrict__ x,
    const float* __restrict__ Wq,
    const float* __restrict__ Wk,
    const float* __restrict__ Wv)
{
    __shared__ float4 sX[32 * 33];
    __shared__ float4 sW[128 * 12];
    const int tid  = threadIdx.x;
    const int tok0 = blockIdx.x * 32;

    const float4* xg = reinterpret_cast<const float4*>(x) + (size_t)tok0 * 32;
#pragma unroll
    for (int i = 0; i < 8; i++) {
        int idx = i * 128 + tid;
        sX[(idx >> 5) * 33 + (idx & 31)] = xg[idx];
    }
    const float4* wq4 = reinterpret_cast<const float4*>(Wq);
    const float4* wk4 = reinterpret_cast<const float4*>(Wk);
    const float4* wv4 = reinterpret_cast<const float4*>(Wv);
#pragma unroll
    for (int i = 0; i < 12; i++) {
        int idx = i * 128 + tid;
        int e = idx / 12, c4 = idx % 12;
        float4 w = (c4 < 4) ? wq4[e * 4 + c4]
                 : (c4 < 8) ? wk4[e * 4 + (c4 - 4)]
                            : wv4[e * 4 + (c4 - 8)];
        sW[e * 12 + c4] = w;
    }
    __syncthreads();

    const int og = tid & 3;
    const int tg = tid >> 2;
    u64 acc[6] = {0ull, 0ull, 0ull, 0ull, 0ull, 0ull};

#pragma unroll 8
    for (int e4 = 0; e4 < 32; e4++) {
        float4 xv = sX[tg * 33 + e4];
        float xs[4] = {xv.x, xv.y, xv.z, xv.w};
#pragma unroll
        for (int u = 0; u < 4; u++) {
            u64 xx = pack2(xs[u], xs[u]);
            const ulonglong2* wp =
                reinterpret_cast<const ulonglong2*>(&sW[(e4 * 4 + u) * 12 + og * 3]);
            ulonglong2 wa = wp[0], wb = wp[1], wc = wp[2];
            acc[0] = fma2(xx, wa.x, acc[0]);
            acc[1] = fma2(xx, wa.y, acc[1]);
            acc[2] = fma2(xx, wb.x, acc[2]);
            acc[3] = fma2(xx, wb.y, acc[3]);
            acc[4] = fma2(xx, wc.x, acc[4]);
            acc[5] = fma2(xx, wc.y, acc[5]);
        }
    }
    float av[12];
#pragma unroll
    for (int i = 0; i < 6; i++) unpack2(acc[i], av[2 * i], av[2 * i + 1]);

    const int tok = tok0 + tg;
#pragma unroll
    for (int k = 0; k < 3; k++) {
        int c0 = og * 12 + k * 4;
        float* base = (c0 < 16) ? g_Q : (c0 < 32) ? g_K : g_V;
        int h0 = c0 & 15;
        float4 o = make_float4(av[k*4+0], av[k*4+1], av[k*4+2], av[k*4+3]);
        *reinterpret_cast<float4*>(base + (size_t)tok * NH + h0) = o;
    }
}

// ---------------------------------------------------------------------------
// Kernel 2: split-K causal flash attention.
// Job = (b, qt: 64-query tile, kc: 512-key chunk). 640 jobs, heavy first.
// CTA = 128 thr. Thread = (slot=tid>>2, r=tid&3): slot owns queries
// {qt*64+slot, +32} (G=2, K/V reuse), r splits keys 4-way (stride 4).
// Padded smem rows (80B) -> the 4 r-groups hit disjoint bank quads.
// Emits partial (m, l, a[16]) per query to scratch; combine_kernel merges.
// ---------------------------------------------------------------------------
__device__ __forceinline__ void upd(
    float s, float& m, float& l, u64* __restrict__ a,
    const ulonglong2& v0, const ulonglong2& v1,
    const ulonglong2& v2, const ulonglong2& v3)
{
    if (s > m) {                 // rare: new running max
        float c = ex2f(m - s);
        m = s;
        l = fmaf(l, c, 1.f);
        u64 cc = pack2(c, c);
        a[0] = fma2(a[0], cc, v0.x); a[1] = fma2(a[1], cc, v0.y);
        a[2] = fma2(a[2], cc, v1.x); a[3] = fma2(a[3], cc, v1.y);
        a[4] = fma2(a[4], cc, v2.x); a[5] = fma2(a[5], cc, v2.y);
        a[6] = fma2(a[6], cc, v3.x); a[7] = fma2(a[7], cc, v3.y);
    } else {                     // common: 1 MUFU + 1 FADD + 8 fma2
        float p = ex2f(s - m);
        l += p;
        u64 pp = pack2(p, p);
        a[0] = fma2(pp, v0.x, a[0]); a[1] = fma2(pp, v0.y, a[1]);
        a[2] = fma2(pp, v1.x, a[2]); a[3] = fma2(pp, v1.y, a[3]);
        a[4] = fma2(pp, v2.x, a[4]); a[5] = fma2(pp, v2.y, a[5]);
        a[6] = fma2(pp, v3.x, a[6]); a[7] = fma2(pp, v3.y, a[7]);
    }
}

__global__ __launch_bounds__(128, 4) void attn_kernel()
{
    __shared__ float4 sKf[128 * 5];   // 128 key rows, 80B stride
    __shared__ float4 sVf[128 * 5];

    // job decode: b interleaved in low bits; jr descending-weight order
    const int bid = blockIdx.x;           // 0..639
    const int b   = bid & 7;
    const int jr  = 79 - (bid >> 3);      // 0..79; jr>=48 -> heaviest group
    int qt, kc;
    if (jr < 8)       { qt = jr;                 kc = 0; }
    else if (jr < 24) { int t = jr - 8;  qt = 8  + (t >> 1); kc = t & 1; }
    else if (jr < 48) { int t = jr - 24; int d = t / 3; qt = 16 + d; kc = t - 3 * d; }
    else              { int t = jr - 48; qt = 24 + (t >> 2); kc = t & 3; }

    const int tid  = threadIdx.x;
    const int r    = tid & 3;
    const int slot = tid >> 2;            // 0..31
    const int qg0  = qt * 64 + slot;
    const int qg1  = qg0 + 32;
    const int ks0  = kc << 9;             // chunk key base
    const bool last = (kc == (qt >> 3));
    const int ntiles = last ? (((qt & 7) >> 1) + 1) : 4;

    const float SC = 0.25f * 1.44269504088896340736f;  // H^-0.5 * log2(e)
    u64 q[16];
    {
        const float4* qp0 = reinterpret_cast<const float4*>(g_Q + ((size_t)b * NT + qg0) * NH);
        const float4* qp1 = reinterpret_cast<const float4*>(g_Q + ((size_t)b * NT + qg1) * NH);
#pragma unroll
        for (int i = 0; i < 4; i++) {
            float4 t0 = qp0[i], t1 = qp1[i];
            q[2*i]     = pack2(t0.x * SC, t0.y * SC);
            q[2*i+1]   = pack2(t0.z * SC, t0.w * SC);
            q[8+2*i]   = pack2(t1.x * SC, t1.y * SC);
            q[8+2*i+1] = pack2(t1.z * SC, t1.w * SC);
        }
    }

    float m0 = -1e30f, l0 = 0.f, m1 = -1e30f, l1 = 0.f;
    u64 a[16];
#pragma unroll
    for (int i = 0; i < 16; i++) a[i] = 0ull;

    const float4* Kg = reinterpret_cast<const float4*>(g_K + (size_t)b * NT * NH);
    const float4* Vg = reinterpret_cast<const float4*>(g_V + (size_t)b * NT * NH);
    const ulonglong2* sK2 = reinterpret_cast<const ulonglong2*>(sKf);
    const ulonglong2* sV2 = reinterpret_cast<const ulonglong2*>(sVf);

    for (int kt = 0; kt < ntiles; kt++) {
        const int kb = ks0 + (kt << 7);   // tile key base
#pragma unroll
        for (int i = 0; i < 4; i++) {
            int idx = i * 128 + tid;                  // 0..511 float4
            int dst = (idx >> 2) * 5 + (idx & 3);     // padded row
            sKf[dst] = Kg[(size_t)kb * 4 + idx];
            sVf[dst] = Vg[(size_t)kb * 4 + idx];
        }
        __syncthreads();

        if (kb + 127 <= qt * 64) {
            // warp-uniform full tile: 32 keys/thread, both queries unmasked
#pragma unroll 2
            for (int jj = 0; jj < 32; jj++) {
                int j = 4 * jj + r;
                ulonglong2 k0 = sK2[j*5+0], k1 = sK2[j*5+1],
                           k2 = sK2[j*5+2], k3 = sK2[j*5+3];
                u64 c0 = fma2(q[0], k0.x, fma2(q[2], k1.x, fma2(q[4], k2.x, mul2(q[6],  k3.x))));
                u64 c1 = fma2(q[1], k0.y, fma2(q[3], k1.y, fma2(q[5], k2.y, mul2(q[7],  k3.y))));
                u64 d0 = fma2(q[8], k0.x, fma2(q[10],k1.x, fma2(q[12],k2.x, mul2(q[14], k3.x))));
                u64 d1 = fma2(q[9], k0.y, fma2(q[11],k1.y, fma2(q[13],k2.y, mul2(q[15], k3.y))));
                float slo, shi, tlo, thi;
                unpack2(add2(c0, c1), slo, shi);
                unpack2(add2(d0, d1), tlo, thi);
                float s0 = slo + shi, s1 = tlo + thi;
                ulonglong2 v0 = sV2[j*5+0], v1 = sV2[j*5+1],
                           v2 = sV2[j*5+2], v3 = sV2[j*5+3];
                upd(s0, m0, l0, a,     v0, v1, v2, v3);
                upd(s1, m1, l1, a + 8, v0, v1, v2, v3);
            }
        } else {
            // diagonal tile
            const int jlim0 = qg0 - kb;
            const int jm1   = min(qg1 - kb, 127);
            for (int j = r; j <= jm1; j += 4) {
                ulonglong2 k0 = sK2[j*5+0], k1 = sK2[j*5+1],
                           k2 = sK2[j*5+2], k3 = sK2[j*5+3];
                u64 c0 = fma2(q[0], k0.x, fma2(q[2], k1.x, fma2(q[4], k2.x, mul2(q[6],  k3.x))));
                u64 c1 = fma2(q[1], k0.y, fma2(q[3], k1.y, fma2(q[5], k2.y, mul2(q[7],  k3.y))));
                u64 d0 = fma2(q[8], k0.x, fma2(q[10],k1.x, fma2(q[12],k2.x, mul2(q[14], k3.x))));
                u64 d1 = fma2(q[9], k0.y, fma2(q[11],k1.y, fma2(q[13],k2.y, mul2(q[15], k3.y))));
                float slo, shi, tlo, thi;
                unpack2(add2(c0, c1), slo, shi);
                unpack2(add2(d0, d1), tlo, thi);
                float s0 = slo + shi, s1 = tlo + thi;
                ulonglong2 v0 = sV2[j*5+0], v1 = sV2[j*5+1],
                           v2 = sV2[j*5+2], v3 = sV2[j*5+3];
                if (j <= jlim0) upd(s0, m0, l0, a, v0, v1, v2, v3);
                upd(s1, m1, l1, a + 8, v0, v1, v2, v3);
            }
        }
        __syncthreads();
    }

    // combine the 4 key-split lanes (tid&3) via xor-1, xor-2 tree
    const unsigned FULL = 0xffffffffu;
#pragma unroll
    for (int d = 1; d <= 2; d <<= 1) {
        float mo0 = __shfl_xor_sync(FULL, m0, d);
        float lo0 = __shfl_xor_sync(FULL, l0, d);
        float mo1 = __shfl_xor_sync(FULL, m1, d);
        float lo1 = __shfl_xor_sync(FULL, l1, d);
        float mx0 = fmaxf(m0, mo0), mx1 = fmaxf(m1, mo1);
        float cs0 = ex2f(m0 - mx0), co0 = ex2f(mo0 - mx0);
        float cs1 = ex2f(m1 - mx1), co1 = ex2f(mo1 - mx1);
        l0 = fmaf(l0, cs0, lo0 * co0);
        l1 = fmaf(l1, cs1, lo1 * co1);
        m0 = mx0; m1 = mx1;
        u64 csp0 = pack2(cs0, cs0), cop0 = pack2(co0, co0);
        u64 csp1 = pack2(cs1, cs1), cop1 = pack2(co1, co1);
#pragma unroll
        for (int i = 0; i < 8; i++) {
            u64 o0 = __shfl_xor_sync(FULL, a[i],     d);
            u64 o1 = __shfl_xor_sync(FULL, a[i + 8], d);
            a[i]     = fma2(a[i],     csp0, mul2(o0, cop0));
            a[i + 8] = fma2(a[i + 8], csp1, mul2(o1, cop1));
        }
    }

    if (r == 0) {
        const int jid = ((b * 32 + qt) << 2) + kc;
        g_pm[jid * 64 + slot]      = m0;
        g_pm[jid * 64 + slot + 32] = m1;
        g_pl[jid * 64 + slot]      = l0;
        g_pl[jid * 64 + slot + 32] = l1;
        float oc[32];
#pragma unroll
        for (int i = 0; i < 8; i++) {
            unpack2(a[i],     oc[2*i],    oc[2*i+1]);
            unpack2(a[i + 8], oc[16+2*i], oc[16+2*i+1]);
        }
        float4* p0 = reinterpret_cast<float4*>(&g_pa[(size_t)(jid * 64 + slot) * 16]);
        float4* p1 = reinterpret_cast<float4*>(&g_pa[(size_t)(jid * 64 + slot + 32) * 16]);
#pragma unroll
        for (int i = 0; i < 4; i++) {
            p0[i] = make_float4(oc[4*i],    oc[4*i+1],    oc[4*i+2],    oc[4*i+3]);
            p1[i] = make_float4(oc[16+4*i], oc[16+4*i+1], oc[16+4*i+2], oc[16+4*i+3]);
        }
    }
}

// ---------------------------------------------------------------------------
// Kernel 3: merge <=4 split-K partials per query and normalize.
// grid = 256 (b,qt), block = 64 (one thread per query).
// ---------------------------------------------------------------------------
__global__ __launch_bounds__(64, 8) void combine_kernel(float* __restrict__ out)
{
    const int bq = blockIdx.x;            // 0..255
    const int b  = bq >> 5, qt = bq & 31;
    const int ql = threadIdx.x;           // 0..63
    const int nc = (qt >> 3) + 1;
    const int base = (b * 32 + qt) << 2;

    float M = -1e30f;
    for (int c = 0; c < nc; c++)
        M = fmaxf(M, g_pm[(base + c) * 64 + ql]);

    float L = 0.f;
    float acc[16];
#pragma unroll
    for (int i = 0; i < 16; i++) acc[i] = 0.f;

    for (int c = 0; c < nc; c++) {
        float sc = ex2f(g_pm[(base + c) * 64 + ql] - M);
        L = fmaf(g_pl[(base + c) * 64 + ql], sc, L);
        const float4* pa = reinterpret_cast<const float4*>(
            &g_pa[(size_t)((base + c) * 64 + ql) * 16]);
#pragma unroll
        for (int i = 0; i < 4; i++) {
            float4 v = pa[i];
            acc[4*i+0] = fmaf(v.x, sc, acc[4*i+0]);
            acc[4*i+1] = fmaf(v.y, sc, acc[4*i+1]);
            acc[4*i+2] = fmaf(v.z, sc, acc[4*i+2]);
            acc[4*i+3] = fmaf(v.w, sc, acc[4*i+3]);
        }
    }
    float inv = 1.0f / L;
    float4* op = reinterpret_cast<float4*>(out + ((size_t)b * NT + qt * 64 + ql) * NH);
#pragma unroll
    for (int i = 0; i < 4; i++)
        op[i] = make_float4(acc[4*i] * inv, acc[4*i+1] * inv,
                            acc[4*i+2] * inv, acc[4*i+3] * inv);
}

extern "C" void kernel_launch(void* const* d_in, const int* in_sizes, int n_in,
                              void* d_out, int out_size)
{
    const float* x  = (const float*)d_in[0];
    const float* Wq = (const float*)d_in[1];
    const float* Wk = (const float*)d_in[2];
    const float* Wv = (const float*)d_in[3];
    float* out = (float*)d_out;

    qkv_kernel<<<512, 128>>>(x, Wq, Wk, Wv);   // 16384 tokens / 32 per CTA
    attn_kernel<<<640, 128>>>();               // split-K jobs, heavy first
    combine_kernel<<<256, 64>>>(out);          // merge + normalize
}

// round 6
// speedup vs baseline: 2.6731x; 1.1122x over previous
#include <cuda_runtime.h>

#define NB 8
#define NT 2048
#define NE 128
#define NH 16

// Q/K/V scratch + split-K partials (allocation-free: __device__ globals)
__device__ float g_Q[NB * NT * NH];
__device__ float g_K[NB * NT * NH];
__device__ float g_V[NB * NT * NH];
// partial flash state per (job=(b*32+qt)*4+kc, query): m, l, a[16]
__device__ float g_pm[8 * 32 * 4 * 64];
__device__ float g_pl[8 * 32 * 4 * 64];
__device__ float g_pa[8 * 32 * 4 * 64 * 16];

typedef unsigned long long u64;

__device__ __forceinline__ float ex2f(float x) {
    float y;
    asm("ex2.approx.ftz.f32 %0, %1;" : "=f"(y) : "f"(x));
    return y;
}
// Blackwell packed fp32x2 (2x fp32 FMA throughput; ptxas never auto-fuses)
__device__ __forceinline__ u64 fma2(u64 a, u64 b, u64 c) {
    u64 d; asm("fma.rn.f32x2 %0, %1, %2, %3;" : "=l"(d) : "l"(a), "l"(b), "l"(c)); return d;
}
__device__ __forceinline__ u64 mul2(u64 a, u64 b) {
    u64 d; asm("mul.rn.f32x2 %0, %1, %2;" : "=l"(d) : "l"(a), "l"(b)); return d;
}
__device__ __forceinline__ u64 add2(u64 a, u64 b) {
    u64 d; asm("add.rn.f32x2 %0, %1, %2;" : "=l"(d) : "l"(a), "l"(b)); return d;
}
__device__ __forceinline__ u64 pack2(float lo, float hi) {
    u64 r; asm("mov.b64 %0, {%1,%2};" : "=l"(r) : "f"(lo), "f"(hi)); return r;
}
__device__ __forceinline__ void unpack2(u64 v, float& lo, float& hi) {
    asm("mov.b64 {%0,%1}, %2;" : "=f"(lo), "=f"(hi) : "l"(v));
}

// ---------------------------------------------------------------------------
// Kernel 1: fused QKV projection. 32 tokens/CTA.
// og = warp id (warp-uniform) -> ALL W shared-loads are broadcasts (16B/warp
// through the crossbar instead of 512B). x reads: stride-33 float4,
// conflict-free per 8-lane phase.
// ---------------------------------------------------------------------------
__global__ __launch_bounds__(128, 3) void qkv_kernel(
    const float* __restrict__ x,
    const float* __restrict__ Wq,
    const float* __restrict__ Wk,
    const float* __restrict__ Wv)
{
    __shared__ float4 sX[32 * 33];
    __shared__ float4 sW[128 * 12];
    const int tid  = threadIdx.x;
    const int tok0 = blockIdx.x * 32;

    const float4* xg = reinterpret_cast<const float4*>(x) + (size_t)tok0 * 32;
#pragma unroll
    for (int i = 0; i < 8; i++) {
        int idx = i * 128 + tid;
        sX[(idx >> 5) * 33 + (idx & 31)] = xg[idx];
    }
    const float4* wq4 = reinterpret_cast<const float4*>(Wq);
    const float4* wk4 = reinterpret_cast<const float4*>(Wk);
    const float4* wv4 = reinterpret_cast<const float4*>(Wv);
#pragma unroll
    for (int i = 0; i < 12; i++) {
        int idx = i * 128 + tid;
        int e = idx / 12, c4 = idx % 12;
        float4 w = (c4 < 4) ? wq4[e * 4 + c4]
                 : (c4 < 8) ? wk4[e * 4 + (c4 - 4)]
                            : wv4[e * 4 + (c4 - 8)];
        sW[e * 12 + c4] = w;
    }
    __syncthreads();

    const int og = tid >> 5;     // warp-uniform output group (12 cols)
    const int tg = tid & 31;     // token within tile = lane
    u64 acc[6] = {0ull, 0ull, 0ull, 0ull, 0ull, 0ull};

#pragma unroll 8
    for (int e4 = 0; e4 < 32; e4++) {
        float4 xv = sX[tg * 33 + e4];
        float xs[4] = {xv.x, xv.y, xv.z, xv.w};
#pragma unroll
        for (int u = 0; u < 4; u++) {
            u64 xx = pack2(xs[u], xs[u]);
            const ulonglong2* wp =
                reinterpret_cast<const ulonglong2*>(&sW[(e4 * 4 + u) * 12 + og * 3]);
            ulonglong2 wa = wp[0], wb = wp[1], wc = wp[2];   // broadcast LDS
            acc[0] = fma2(xx, wa.x, acc[0]);
            acc[1] = fma2(xx, wa.y, acc[1]);
            acc[2] = fma2(xx, wb.x, acc[2]);
            acc[3] = fma2(xx, wb.y, acc[3]);
            acc[4] = fma2(xx, wc.x, acc[4]);
            acc[5] = fma2(xx, wc.y, acc[5]);
        }
    }
    float av[12];
#pragma unroll
    for (int i = 0; i < 6; i++) unpack2(acc[i], av[2 * i], av[2 * i + 1]);

    const int tok = tok0 + tg;
#pragma unroll
    for (int k = 0; k < 3; k++) {
        int c0 = og * 12 + k * 4;
        float* base = (c0 < 16) ? g_Q : (c0 < 32) ? g_K : g_V;
        int h0 = c0 & 15;
        float4 o = make_float4(av[k*4+0], av[k*4+1], av[k*4+2], av[k*4+3]);
        *reinterpret_cast<float4*>(base + (size_t)tok * NH + h0) = o;
    }
}

// ---------------------------------------------------------------------------
// Kernel 2: split-K causal flash attention.
// Job = (b, qt: 64-query tile, kc: 512-key chunk). 640 jobs, heavy first.
// CTA = 128 thr. Warp = key phase r (keys j === r mod 4, warp-uniform ->
// K/V loads are broadcasts). Lane = query slot: owns {qt*64+lane, +32}.
// Cross-warp merge via smem (reusing the K/V tile space).
// ---------------------------------------------------------------------------
__device__ __forceinline__ void upd(
    float s, float& m, float& l, u64* __restrict__ a,
    const ulonglong2& v0, const ulonglong2& v1,
    const ulonglong2& v2, const ulonglong2& v3)
{
    if (s > m) {                 // rare: new running max
        float c = ex2f(m - s);
        m = s;
        l = fmaf(l, c, 1.f);
        u64 cc = pack2(c, c);
        a[0] = fma2(a[0], cc, v0.x); a[1] = fma2(a[1], cc, v0.y);
        a[2] = fma2(a[2], cc, v1.x); a[3] = fma2(a[3], cc, v1.y);
        a[4] = fma2(a[4], cc, v2.x); a[5] = fma2(a[5], cc, v2.y);
        a[6] = fma2(a[6], cc, v3.x); a[7] = fma2(a[7], cc, v3.y);
    } else {                     // common: 1 MUFU + 1 FADD + 8 fma2
        float p = ex2f(s - m);
        l += p;
        u64 pp = pack2(p, p);
        a[0] = fma2(pp, v0.x, a[0]); a[1] = fma2(pp, v0.y, a[1]);
        a[2] = fma2(pp, v1.x, a[2]); a[3] = fma2(pp, v1.y, a[3]);
        a[4] = fma2(pp, v2.x, a[4]); a[5] = fma2(pp, v2.y, a[5]);
        a[6] = fma2(pp, v3.x, a[6]); a[7] = fma2(pp, v3.y, a[7]);
    }
}

__global__ __launch_bounds__(128, 4) void attn_kernel()
{
    __shared__ float4 sbuf[1024];    // K[512] | V[512]; reused for combine
    float4* sK4 = sbuf;
    float4* sV4 = sbuf + 512;

    // job decode: b interleaved in low bits; jr descending-weight order
    const int bid = blockIdx.x;           // 0..639
    const int b   = bid & 7;
    const int jr  = 79 - (bid >> 3);      // 0..79; jr>=48 -> heaviest group
    int qt, kc;
    if (jr < 8)       { qt = jr;                 kc = 0; }
    else if (jr < 24) { int t = jr - 8;  qt = 8  + (t >> 1); kc = t & 1; }
    else if (jr < 48) { int t = jr - 24; int d = t / 3; qt = 16 + d; kc = t - 3 * d; }
    else              { int t = jr - 48; qt = 24 + (t >> 2); kc = t & 3; }

    const int tid  = threadIdx.x;
    const int r    = tid >> 5;            // warp id = key phase (uniform)
    const int lane = tid & 31;            // query slot
    const int qg0  = qt * 64 + lane;
    const int qg1  = qg0 + 32;
    const int ks0  = kc << 9;             // chunk key base
    const bool last = (kc == (qt >> 3));
    const int ntiles = last ? (((qt & 7) >> 1) + 1) : 4;

    const float SC = 0.25f * 1.44269504088896340736f;  // H^-0.5 * log2(e)
    u64 q[16];
    {
        const float4* qp0 = reinterpret_cast<const float4*>(g_Q + ((size_t)b * NT + qg0) * NH);
        const float4* qp1 = reinterpret_cast<const float4*>(g_Q + ((size_t)b * NT + qg1) * NH);
#pragma unroll
        for (int i = 0; i < 4; i++) {
            float4 t0 = qp0[i], t1 = qp1[i];
            q[2*i]     = pack2(t0.x * SC, t0.y * SC);
            q[2*i+1]   = pack2(t0.z * SC, t0.w * SC);
            q[8+2*i]   = pack2(t1.x * SC, t1.y * SC);
            q[8+2*i+1] = pack2(t1.z * SC, t1.w * SC);
        }
    }

    float m0 = -1e30f, l0 = 0.f, m1 = -1e30f, l1 = 0.f;
    u64 a[16];
#pragma unroll
    for (int i = 0; i < 16; i++) a[i] = 0ull;

    const float4* Kg = reinterpret_cast<const float4*>(g_K + (size_t)b * NT * NH);
    const float4* Vg = reinterpret_cast<const float4*>(g_V + (size_t)b * NT * NH);
    const ulonglong2* sK2 = reinterpret_cast<const ulonglong2*>(sK4);
    const ulonglong2* sV2 = reinterpret_cast<const ulonglong2*>(sV4);

    for (int kt = 0; kt < ntiles; kt++) {
        const int kb = ks0 + (kt << 7);   // tile key base
#pragma unroll
        for (int i = 0; i < 4; i++) {
            int idx = i * 128 + tid;                  // 0..511 float4
            sK4[idx] = Kg[(size_t)kb * 4 + idx];
            sV4[idx] = Vg[(size_t)kb * 4 + idx];
        }
        __syncthreads();

        if (kb + 127 <= qt * 64) {
            // full tile: 32 keys/warp, all lanes unmasked
#pragma unroll 4
            for (int jj = 0; jj < 32; jj++) {
                int j = 4 * jj + r;                    // warp-uniform key
                ulonglong2 k0 = sK2[j*4+0], k1 = sK2[j*4+1],
                           k2 = sK2[j*4+2], k3 = sK2[j*4+3];   // broadcast
                u64 c0 = fma2(q[0], k0.x, fma2(q[2], k1.x, fma2(q[4], k2.x, mul2(q[6],  k3.x))));
                u64 c1 = fma2(q[1], k0.y, fma2(q[3], k1.y, fma2(q[5], k2.y, mul2(q[7],  k3.y))));
                u64 d0 = fma2(q[8], k0.x, fma2(q[10],k1.x, fma2(q[12],k2.x, mul2(q[14], k3.x))));
                u64 d1 = fma2(q[9], k0.y, fma2(q[11],k1.y, fma2(q[13],k2.y, mul2(q[15], k3.y))));
                float slo, shi, tlo, thi;
                unpack2(add2(c0, c1), slo, shi);
                unpack2(add2(d0, d1), tlo, thi);
                float s0 = slo + shi, s1 = tlo + thi;
                ulonglong2 v0 = sV2[j*4+0], v1 = sV2[j*4+1],
                           v2 = sV2[j*4+2], v3 = sV2[j*4+3];   // broadcast
                upd(s0, m0, l0, a,     v0, v1, v2, v3);
                upd(s1, m1, l1, a + 8, v0, v1, v2, v3);
            }
        } else {
            // diagonal tile: warp-uniform bound, per-lane causal predicates
            const int jmax = min(127, qt * 64 + 63 - kb);
            for (int j = r; j <= jmax; j += 4) {
                ulonglong2 k0 = sK2[j*4+0], k1 = sK2[j*4+1],
                           k2 = sK2[j*4+2], k3 = sK2[j*4+3];
                u64 c0 = fma2(q[0], k0.x, fma2(q[2], k1.x, fma2(q[4], k2.x, mul2(q[6],  k3.x))));
                u64 c1 = fma2(q[1], k0.y, fma2(q[3], k1.y, fma2(q[5], k2.y, mul2(q[7],  k3.y))));
                u64 d0 = fma2(q[8], k0.x, fma2(q[10],k1.x, fma2(q[12],k2.x, mul2(q[14], k3.x))));
                u64 d1 = fma2(q[9], k0.y, fma2(q[11],k1.y, fma2(q[13],k2.y, mul2(q[15], k3.y))));
                float slo, shi, tlo, thi;
                unpack2(add2(c0, c1), slo, shi);
                unpack2(add2(d0, d1), tlo, thi);
                float s0 = slo + shi, s1 = tlo + thi;
                ulonglong2 v0 = sV2[j*4+0], v1 = sV2[j*4+1],
                           v2 = sV2[j*4+2], v3 = sV2[j*4+3];
                int kj = kb + j;
                if (kj <= qg0) upd(s0, m0, l0, a,     v0, v1, v2, v3);
                if (kj <= qg1) upd(s1, m1, l1, a + 8, v0, v1, v2, v3);
            }
        }
        __syncthreads();
    }

    // cross-warp combine: warps 1..3 stage (a, m, l) in smem, warp 0 merges.
    // slot layout: [(w-1)*2+qi][lane] of 5 ulonglong2 (stride 5 -> conflict-free)
    ulonglong2* cb = reinterpret_cast<ulonglong2*>(sbuf);
    if (r > 0) {
#pragma unroll
        for (int qi = 0; qi < 2; qi++) {
            int base = ((r - 1) * 2 + qi) * 160 + lane * 5;
            const u64* aq = a + qi * 8;
            cb[base + 0] = make_ulonglong2(aq[0], aq[1]);
            cb[base + 1] = make_ulonglong2(aq[2], aq[3]);
            cb[base + 2] = make_ulonglong2(aq[4], aq[5]);
            cb[base + 3] = make_ulonglong2(aq[6], aq[7]);
            cb[base + 4] = make_ulonglong2(
                pack2(qi == 0 ? m0 : m1, qi == 0 ? l0 : l1), 0ull);
        }
    }
    __syncthreads();

    if (r == 0) {
#pragma unroll
        for (int w = 1; w < 4; w++) {
#pragma unroll
            for (int qi = 0; qi < 2; qi++) {
                int base = ((w - 1) * 2 + qi) * 160 + lane * 5;
                float mw, lw;
                unpack2(cb[base + 4].x, mw, lw);
                float& m = (qi == 0) ? m0 : m1;
                float& l = (qi == 0) ? l0 : l1;
                u64* aq = a + qi * 8;
                float mx = fmaxf(m, mw);
                float cs = ex2f(m - mx), co = ex2f(mw - mx);
                l = fmaf(l, cs, lw * co);
                m = mx;
                u64 csp = pack2(cs, cs), cop = pack2(co, co);
#pragma unroll
                for (int i = 0; i < 4; i++) {
                    ulonglong2 t = cb[base + i];
                    aq[2*i]   = fma2(aq[2*i],   csp, mul2(t.x, cop));
                    aq[2*i+1] = fma2(aq[2*i+1], csp, mul2(t.y, cop));
                }
            }
        }
        // emit split-K partial
        const int jid = ((b * 32 + qt) << 2) + kc;
        g_pm[jid * 64 + lane]      = m0;
        g_pm[jid * 64 + lane + 32] = m1;
        g_pl[jid * 64 + lane]      = l0;
        g_pl[jid * 64 + lane + 32] = l1;
        float oc[32];
#pragma unroll
        for (int i = 0; i < 8; i++) {
            unpack2(a[i],     oc[2*i],    oc[2*i+1]);
            unpack2(a[i + 8], oc[16+2*i], oc[16+2*i+1]);
        }
        float4* p0 = reinterpret_cast<float4*>(&g_pa[(size_t)(jid * 64 + lane) * 16]);
        float4* p1 = reinterpret_cast<float4*>(&g_pa[(size_t)(jid * 64 + lane + 32) * 16]);
#pragma unroll
        for (int i = 0; i < 4; i++) {
            p0[i] = make_float4(oc[4*i],    oc[4*i+1],    oc[4*i+2],    oc[4*i+3]);
            p1[i] = make_float4(oc[16+4*i], oc[16+4*i+1], oc[16+4*i+2], oc[16+4*i+3]);
        }
    }
}

// ---------------------------------------------------------------------------
// Kernel 3: merge <=4 split-K partials per query and normalize.
// grid = 256 (b,qt), block = 64 (one thread per query).
// ---------------------------------------------------------------------------
__global__ __launch_bounds__(64, 8) void combine_kernel(float* __restrict__ out)
{
    const int bq = blockIdx.x;            // 0..255
    const int b  = bq >> 5, qt = bq & 31;
    const int ql = threadIdx.x;           // 0..63
    const int nc = (qt >> 3) + 1;
    const int base = (b * 32 + qt) << 2;

    float M = -1e30f;
    for (int c = 0; c < nc; c++)
        M = fmaxf(M, g_pm[(base + c) * 64 + ql]);

    float L = 0.f;
    float acc[16];
#pragma unroll
    for (int i = 0; i < 16; i++) acc[i] = 0.f;

    for (int c = 0; c < nc; c++) {
        float sc = ex2f(g_pm[(base + c) * 64 + ql] - M);
        L = fmaf(g_pl[(base + c) * 64 + ql], sc, L);
        const float4* pa = reinterpret_cast<const float4*>(
            &g_pa[(size_t)((base + c) * 64 + ql) * 16]);
#pragma unroll
        for (int i = 0; i < 4; i++) {
            float4 v = pa[i];
            acc[4*i+0] = fmaf(v.x, sc, acc[4*i+0]);
            acc[4*i+1] = fmaf(v.y, sc, acc[4*i+1]);
            acc[4*i+2] = fmaf(v.z, sc, acc[4*i+2]);
            acc[4*i+3] = fmaf(v.w, sc, acc[4*i+3]);
        }
    }
    float inv = 1.0f / L;
    float4* op = reinterpret_cast<float4*>(out + ((size_t)b * NT + qt * 64 + ql) * NH);
#pragma unroll
    for (int i = 0; i < 4; i++)
        op[i] = make_float4(acc[4*i] * inv, acc[4*i+1] * inv,
                            acc[4*i+2] * inv, acc[4*i+3] * inv);
}

extern "C" void kernel_launch(void* const* d_in, const int* in_sizes, int n_in,
                              void* d_out, int out_size)
{
    const float* x  = (const float*)d_in[0];
    const float* Wq = (const float*)d_in[1];
    const float* Wk = (const float*)d_in[2];
    const float* Wv = (const float*)d_in[3];
    float* out = (float*)d_out;

    qkv_kernel<<<512, 128>>>(x, Wq, Wk, Wv);   // 16384 tokens / 32 per CTA
    attn_kernel<<<640, 128>>>();               // split-K jobs, heavy first
    combine_kernel<<<256, 64>>>(out);          // merge + normalize
}

// round 7
// speedup vs baseline: 3.0195x; 1.1296x over previous
#include <cuda_runtime.h>

#define NB 8
#define NT 2048
#define NE 128
#define NH 16

// Q/K/V scratch + split-K partials (allocation-free: __device__ globals)
__device__ float g_Q[NB * NT * NH];
__device__ float g_K[NB * NT * NH];
__device__ float g_V[NB * NT * NH];
// partial flash state per (job=(b*32+qt)*4+kc, query): m, l, a[16]
__device__ float g_pm[8 * 32 * 4 * 64];
__device__ float g_pl[8 * 32 * 4 * 64];
__device__ float g_pa[8 * 32 * 4 * 64 * 16];

typedef unsigned long long u64;

__device__ __forceinline__ float ex2f(float x) {
    float y;
    asm("ex2.approx.ftz.f32 %0, %1;" : "=f"(y) : "f"(x));
    return y;
}
// Blackwell packed fp32x2 (2x fp32 FMA throughput; ptxas never auto-fuses)
__device__ __forceinline__ u64 fma2(u64 a, u64 b, u64 c) {
    u64 d; asm("fma.rn.f32x2 %0, %1, %2, %3;" : "=l"(d) : "l"(a), "l"(b), "l"(c)); return d;
}
__device__ __forceinline__ u64 mul2(u64 a, u64 b) {
    u64 d; asm("mul.rn.f32x2 %0, %1, %2;" : "=l"(d) : "l"(a), "l"(b)); return d;
}
__device__ __forceinline__ u64 add2(u64 a, u64 b) {
    u64 d; asm("add.rn.f32x2 %0, %1, %2;" : "=l"(d) : "l"(a), "l"(b)); return d;
}
__device__ __forceinline__ u64 pack2(float lo, float hi) {
    u64 r; asm("mov.b64 %0, {%1,%2};" : "=l"(r) : "f"(lo), "f"(hi)); return r;
}
__device__ __forceinline__ void unpack2(u64 v, float& lo, float& hi) {
    asm("mov.b64 {%0,%1}, %2;" : "=f"(lo), "=f"(hi) : "l"(v));
}

// ---------------------------------------------------------------------------
// Kernel 1: fused QKV projection. 64 tokens/CTA, G=2 tokens/thread.
// og = warp id (warp-uniform -> W loads are broadcast LDS); e-dim processed
// in two halves so x(17.4KB) + W(24KB) fit static smem.
// Per e-quad: 2 x-LDS + 12 W-LDS feed 48 fma2 (was 13 LDS : 24 fma2).
// ---------------------------------------------------------------------------
__global__ __launch_bounds__(128, 2) void qkv_kernel(
    const float* __restrict__ x,
    const float* __restrict__ Wq,
    const float* __restrict__ Wk,
    const float* __restrict__ Wv)
{
    __shared__ float4 sX[64 * 17];    // 64 tokens x 16 f4 (half of e), pad 17
    __shared__ float4 sW[128 * 12];   // 128 e-rows x 48 floats
    const int tid  = threadIdx.x;
    const int tok0 = blockIdx.x * 64;

    // load W (1536 float4)
    const float4* wq4 = reinterpret_cast<const float4*>(Wq);
    const float4* wk4 = reinterpret_cast<const float4*>(Wk);
    const float4* wv4 = reinterpret_cast<const float4*>(Wv);
#pragma unroll
    for (int i = 0; i < 12; i++) {
        int idx = i * 128 + tid;
        int e = idx / 12, c4 = idx % 12;
        float4 w = (c4 < 4) ? wq4[e * 4 + c4]
                 : (c4 < 8) ? wk4[e * 4 + (c4 - 4)]
                            : wv4[e * 4 + (c4 - 8)];
        sW[e * 12 + c4] = w;
    }

    const int og = tid >> 5;     // warp-uniform output group (12 cols)
    const int tg = tid & 31;     // token slot: owns tg and tg+32
    const float4* xg = reinterpret_cast<const float4*>(x) + (size_t)tok0 * 32;

    u64 acc[12];                 // [0..5] token tg, [6..11] token tg+32
#pragma unroll
    for (int i = 0; i < 12; i++) acc[i] = 0ull;

#pragma unroll
    for (int half = 0; half < 2; half++) {
        __syncthreads();         // first: covers W; later: guards sX reuse
        // load x half: 64 tokens x 16 f4 = 1024 f4 (coalesced 256B runs)
#pragma unroll
        for (int i = 0; i < 8; i++) {
            int idx = i * 128 + tid;
            int row = idx >> 4, col = idx & 15;
            sX[row * 17 + col] = xg[row * 32 + half * 16 + col];
        }
        __syncthreads();

#pragma unroll 4
        for (int e4 = 0; e4 < 16; e4++) {
            float4 xv0 = sX[tg * 17 + e4];
            float4 xv1 = sX[(tg + 32) * 17 + e4];
            float xs0[4] = {xv0.x, xv0.y, xv0.z, xv0.w};
            float xs1[4] = {xv1.x, xv1.y, xv1.z, xv1.w};
            int e = half * 64 + e4 * 4;
#pragma unroll
            for (int u = 0; u < 4; u++) {
                const ulonglong2* wp = reinterpret_cast<const ulonglong2*>(
                    &sW[(e + u) * 12 + og * 3]);
                ulonglong2 wa = wp[0], wb = wp[1], wc = wp[2];  // broadcast
                u64 x0 = pack2(xs0[u], xs0[u]);
                u64 x1 = pack2(xs1[u], xs1[u]);
                acc[0]  = fma2(x0, wa.x, acc[0]);
                acc[1]  = fma2(x0, wa.y, acc[1]);
                acc[2]  = fma2(x0, wb.x, acc[2]);
                acc[3]  = fma2(x0, wb.y, acc[3]);
                acc[4]  = fma2(x0, wc.x, acc[4]);
                acc[5]  = fma2(x0, wc.y, acc[5]);
                acc[6]  = fma2(x1, wa.x, acc[6]);
                acc[7]  = fma2(x1, wa.y, acc[7]);
                acc[8]  = fma2(x1, wb.x, acc[8]);
                acc[9]  = fma2(x1, wb.y, acc[9]);
                acc[10] = fma2(x1, wc.x, acc[10]);
                acc[11] = fma2(x1, wc.y, acc[11]);
            }
        }
    }

    float av[24];
#pragma unroll
    for (int i = 0; i < 12; i++) unpack2(acc[i], av[2 * i], av[2 * i + 1]);

#pragma unroll
    for (int t = 0; t < 2; t++) {
        const int tok = tok0 + tg + t * 32;
        const float* avt = av + t * 12;
#pragma unroll
        for (int k = 0; k < 3; k++) {
            int c0 = og * 12 + k * 4;   // 4-col blocks never straddle a matrix
            float* base = (c0 < 16) ? g_Q : (c0 < 32) ? g_K : g_V;
            int h0 = c0 & 15;
            float4 o = make_float4(avt[k*4+0], avt[k*4+1], avt[k*4+2], avt[k*4+3]);
            *reinterpret_cast<float4*>(base + (size_t)tok * NH + h0) = o;
        }
    }
}

// ---------------------------------------------------------------------------
// Kernel 2: split-K causal flash attention, BRANCHLESS online softmax with
// key-pair batching. Warp = key phase (pairs {2r,2r+1} mod 8, broadcast LDS),
// lane = query slot (owns qt*64+lane and +32).
// ---------------------------------------------------------------------------
__device__ __forceinline__ void scores2(
    const ulonglong2* __restrict__ kp, const u64* __restrict__ q,
    float& s0a, float& s1a, float& s0b, float& s1b)
{
    ulonglong2 a0 = kp[0], a1 = kp[1], a2 = kp[2], a3 = kp[3];
    ulonglong2 b0 = kp[4], b1 = kp[5], b2 = kp[6], b3 = kp[7];
    u64 t; float lo, hi;
    t = fma2(q[0], a0.x, fma2(q[2], a1.x, fma2(q[4], a2.x, mul2(q[6],  a3.x))));
    t = add2(t, fma2(q[1], a0.y, fma2(q[3], a1.y, fma2(q[5], a2.y, mul2(q[7],  a3.y)))));
    unpack2(t, lo, hi); s0a = lo + hi;
    t = fma2(q[8], a0.x, fma2(q[10],a1.x, fma2(q[12],a2.x, mul2(q[14], a3.x))));
    t = add2(t, fma2(q[9], a0.y, fma2(q[11],a1.y, fma2(q[13],a2.y, mul2(q[15], a3.y)))));
    unpack2(t, lo, hi); s1a = lo + hi;
    t = fma2(q[0], b0.x, fma2(q[2], b1.x, fma2(q[4], b2.x, mul2(q[6],  b3.x))));
    t = add2(t, fma2(q[1], b0.y, fma2(q[3], b1.y, fma2(q[5], b2.y, mul2(q[7],  b3.y)))));
    unpack2(t, lo, hi); s0b = lo + hi;
    t = fma2(q[8], b0.x, fma2(q[10],b1.x, fma2(q[12],b2.x, mul2(q[14], b3.x))));
    t = add2(t, fma2(q[9], b0.y, fma2(q[11],b1.y, fma2(q[13],b2.y, mul2(q[15], b3.y)))));
    unpack2(t, lo, hi); s1b = lo + hi;
}

template<bool MASKED>
__device__ __forceinline__ void upd2(
    float sa, float sb, bool oka, bool okb,
    float& m, float& l, u64* __restrict__ a,
    const ulonglong2& va0, const ulonglong2& va1,
    const ulonglong2& va2, const ulonglong2& va3,
    const ulonglong2& vb0, const ulonglong2& vb1,
    const ulonglong2& vb2, const ulonglong2& vb3)
{
    float mnew = fmaxf(m, fmaxf(sa, sb));
    float c  = ex2f(m - mnew);
    float pa = ex2f(sa - mnew);
    float pb = ex2f(sb - mnew);
    if (MASKED) {                 // FSEL, no branch
        pa = oka ? pa : 0.f;
        pb = okb ? pb : 0.f;
    }
    m = mnew;
    l = fmaf(l, c, pa + pb);
    u64 cc = pack2(c, c), pap = pack2(pa, pa), pbp = pack2(pb, pb);
    a[0] = fma2(a[0], cc, fma2(pbp, vb0.x, mul2(pap, va0.x)));
    a[1] = fma2(a[1], cc, fma2(pbp, vb0.y, mul2(pap, va0.y)));
    a[2] = fma2(a[2], cc, fma2(pbp, vb1.x, mul2(pap, va1.x)));
    a[3] = fma2(a[3], cc, fma2(pbp, vb1.y, mul2(pap, va1.y)));
    a[4] = fma2(a[4], cc, fma2(pbp, vb2.x, mul2(pap, va2.x)));
    a[5] = fma2(a[5], cc, fma2(pbp, vb2.y, mul2(pap, va2.y)));
    a[6] = fma2(a[6], cc, fma2(pbp, vb3.x, mul2(pap, va3.x)));
    a[7] = fma2(a[7], cc, fma2(pbp, vb3.y, mul2(pap, va3.y)));
}

__global__ __launch_bounds__(128, 3) void attn_kernel()
{
    __shared__ float4 sbuf[1024];    // K[512] | V[512]; reused for combine
    float4* sK4 = sbuf;
    float4* sV4 = sbuf + 512;

    // job decode: b interleaved in low bits; jr descending-weight order
    const int bid = blockIdx.x;           // 0..639
    const int b   = bid & 7;
    const int jr  = 79 - (bid >> 3);      // 0..79; jr>=48 -> heaviest group
    int qt, kc;
    if (jr < 8)       { qt = jr;                 kc = 0; }
    else if (jr < 24) { int t = jr - 8;  qt = 8  + (t >> 1); kc = t & 1; }
    else if (jr < 48) { int t = jr - 24; int d = t / 3; qt = 16 + d; kc = t - 3 * d; }
    else              { int t = jr - 48; qt = 24 + (t >> 2); kc = t & 3; }

    const int tid  = threadIdx.x;
    const int r    = tid >> 5;            // warp id = key-pair phase (uniform)
    const int lane = tid & 31;            // query slot
    const int qg0  = qt * 64 + lane;
    const int qg1  = qg0 + 32;
    const int ks0  = kc << 9;             // chunk key base
    const bool last = (kc == (qt >> 3));
    const int ntiles = last ? (((qt & 7) >> 1) + 1) : 4;

    const float SC = 0.25f * 1.44269504088896340736f;  // H^-0.5 * log2(e)
    u64 q[16];
    {
        const float4* qp0 = reinterpret_cast<const float4*>(g_Q + ((size_t)b * NT + qg0) * NH);
        const float4* qp1 = reinterpret_cast<const float4*>(g_Q + ((size_t)b * NT + qg1) * NH);
#pragma unroll
        for (int i = 0; i < 4; i++) {
            float4 t0 = qp0[i], t1 = qp1[i];
            q[2*i]     = pack2(t0.x * SC, t0.y * SC);
            q[2*i+1]   = pack2(t0.z * SC, t0.w * SC);
            q[8+2*i]   = pack2(t1.x * SC, t1.y * SC);
            q[8+2*i+1] = pack2(t1.z * SC, t1.w * SC);
        }
    }

    float m0 = -1e30f, l0 = 0.f, m1 = -1e30f, l1 = 0.f;
    u64 a[16];
#pragma unroll
    for (int i = 0; i < 16; i++) a[i] = 0ull;

    const float4* Kg = reinterpret_cast<const float4*>(g_K + (size_t)b * NT * NH);
    const float4* Vg = reinterpret_cast<const float4*>(g_V + (size_t)b * NT * NH);
    const ulonglong2* sK2 = reinterpret_cast<const ulonglong2*>(sK4);
    const ulonglong2* sV2 = reinterpret_cast<const ulonglong2*>(sV4);

    for (int kt = 0; kt < ntiles; kt++) {
        const int kb = ks0 + (kt << 7);   // tile key base
#pragma unroll
        for (int i = 0; i < 4; i++) {
            int idx = i * 128 + tid;
            sK4[idx] = Kg[(size_t)kb * 4 + idx];
            sV4[idx] = Vg[(size_t)kb * 4 + idx];
        }
        __syncthreads();

        if (kb + 127 <= qt * 64) {
            // full tile: 16 key-pairs per warp, no masks
#pragma unroll 2
            for (int jj = 0; jj < 16; jj++) {
                int j0 = 8 * jj + 2 * r;          // warp-uniform
                float s0a, s1a, s0b, s1b;
                scores2(sK2 + j0 * 4, q, s0a, s1a, s0b, s1b);
                const ulonglong2* vp = sV2 + j0 * 4;
                ulonglong2 va0 = vp[0], va1 = vp[1], va2 = vp[2], va3 = vp[3];
                ulonglong2 vb0 = vp[4], vb1 = vp[5], vb2 = vp[6], vb3 = vp[7];
                upd2<false>(s0a, s0b, true, true, m0, l0, a,
                            va0, va1, va2, va3, vb0, vb1, vb2, vb3);
                upd2<false>(s1a, s1b, true, true, m1, l1, a + 8,
                            va0, va1, va2, va3, vb0, vb1, vb2, vb3);
            }
        } else {
            // diagonal tile: per-lane causal masks via FSEL (pa/pb zeroed)
            const int jmax = min(127, qt * 64 + 63 - kb);
            for (int j0 = 2 * r; j0 <= jmax; j0 += 8) {
                float s0a, s1a, s0b, s1b;
                scores2(sK2 + j0 * 4, q, s0a, s1a, s0b, s1b);
                const ulonglong2* vp = sV2 + j0 * 4;
                ulonglong2 va0 = vp[0], va1 = vp[1], va2 = vp[2], va3 = vp[3];
                ulonglong2 vb0 = vp[4], vb1 = vp[5], vb2 = vp[6], vb3 = vp[7];
                int kja = kb + j0, kjb = kja + 1;
                upd2<true>(s0a, s0b, kja <= qg0, kjb <= qg0, m0, l0, a,
                           va0, va1, va2, va3, vb0, vb1, vb2, vb3);
                upd2<true>(s1a, s1b, kja <= qg1, kjb <= qg1, m1, l1, a + 8,
                           va0, va1, va2, va3, vb0, vb1, vb2, vb3);
            }
        }
        __syncthreads();
    }

    // cross-warp combine: warps 1..3 stage (a, m, l) in smem, warp 0 merges.
    ulonglong2* cb = reinterpret_cast<ulonglong2*>(sbuf);
    if (r > 0) {
#pragma unroll
        for (int qi = 0; qi < 2; qi++) {
            int base = ((r - 1) * 2 + qi) * 160 + lane * 5;
            const u64* aq = a + qi * 8;
            cb[base + 0] = make_ulonglong2(aq[0], aq[1]);
            cb[base + 1] = make_ulonglong2(aq[2], aq[3]);
            cb[base + 2] = make_ulonglong2(aq[4], aq[5]);
            cb[base + 3] = make_ulonglong2(aq[6], aq[7]);
            cb[base + 4] = make_ulonglong2(
                pack2(qi == 0 ? m0 : m1, qi == 0 ? l0 : l1), 0ull);
        }
    }
    __syncthreads();

    if (r == 0) {
#pragma unroll
        for (int w = 1; w < 4; w++) {
#pragma unroll
            for (int qi = 0; qi < 2; qi++) {
                int base = ((w - 1) * 2 + qi) * 160 + lane * 5;
                float mw, lw;
                unpack2(cb[base + 4].x, mw, lw);
                float& m = (qi == 0) ? m0 : m1;
                float& l = (qi == 0) ? l0 : l1;
                u64* aq = a + qi * 8;
                float mx = fmaxf(m, mw);
                float cs = ex2f(m - mx), co = ex2f(mw - mx);
                l = fmaf(l, cs, lw * co);
                m = mx;
                u64 csp = pack2(cs, cs), cop = pack2(co, co);
#pragma unroll
                for (int i = 0; i < 4; i++) {
                    ulonglong2 t = cb[base + i];
                    aq[2*i]   = fma2(aq[2*i],   csp, mul2(t.x, cop));
                    aq[2*i+1] = fma2(aq[2*i+1], csp, mul2(t.y, cop));
                }
            }
        }
        // emit split-K partial
        const int jid = ((b * 32 + qt) << 2) + kc;
        g_pm[jid * 64 + lane]      = m0;
        g_pm[jid * 64 + lane + 32] = m1;
        g_pl[jid * 64 + lane]      = l0;
        g_pl[jid * 64 + lane + 32] = l1;
        float oc[32];
#pragma unroll
        for (int i = 0; i < 8; i++) {
            unpack2(a[i],     oc[2*i],    oc[2*i+1]);
            unpack2(a[i + 8], oc[16+2*i], oc[16+2*i+1]);
        }
        float4* p0 = reinterpret_cast<float4*>(&g_pa[(size_t)(jid * 64 + lane) * 16]);
        float4* p1 = reinterpret_cast<float4*>(&g_pa[(size_t)(jid * 64 + lane + 32) * 16]);
#pragma unroll
        for (int i = 0; i < 4; i++) {
            p0[i] = make_float4(oc[4*i],    oc[4*i+1],    oc[4*i+2],    oc[4*i+3]);
            p1[i] = make_float4(oc[16+4*i], oc[16+4*i+1], oc[16+4*i+2], oc[16+4*i+3]);
        }
    }
}

// ---------------------------------------------------------------------------
// Kernel 3: merge <=4 split-K partials per query and normalize.
// ---------------------------------------------------------------------------
__global__ __launch_bounds__(64, 8) void combine_kernel(float* __restrict__ out)
{
    const int bq = blockIdx.x;            // 0..255
    const int b  = bq >> 5, qt = bq & 31;
    const int ql = threadIdx.x;           // 0..63
    const int nc = (qt >> 3) + 1;
    const int base = (b * 32 + qt) << 2;

    float M = -1e30f;
    for (int c = 0; c < nc; c++)
        M = fmaxf(M, g_pm[(base + c) * 64 + ql]);

    float L = 0.f;
    float acc[16];
#pragma unroll
    for (int i = 0; i < 16; i++) acc[i] = 0.f;

    for (int c = 0; c < nc; c++) {
        float sc = ex2f(g_pm[(base + c) * 64 + ql] - M);
        L = fmaf(g_pl[(base + c) * 64 + ql], sc, L);
        const float4* pa = reinterpret_cast<const float4*>(
            &g_pa[(size_t)((base + c) * 64 + ql) * 16]);
#pragma unroll
        for (int i = 0; i < 4; i++) {
            float4 v = pa[i];
            acc[4*i+0] = fmaf(v.x, sc, acc[4*i+0]);
            acc[4*i+1] = fmaf(v.y, sc, acc[4*i+1]);
            acc[4*i+2] = fmaf(v.z, sc, acc[4*i+2]);
            acc[4*i+3] = fmaf(v.w, sc, acc[4*i+3]);
        }
    }
    float inv = 1.0f / L;
    float4* op = reinterpret_cast<float4*>(out + ((size_t)b * NT + qt * 64 + ql) * NH);
#pragma unroll
    for (int i = 0; i < 4; i++)
        op[i] = make_float4(acc[4*i] * inv, acc[4*i+1] * inv,
                            acc[4*i+2] * inv, acc[4*i+3] * inv);
}

extern "C" void kernel_launch(void* const* d_in, const int* in_sizes, int n_in,
                              void* d_out, int out_size)
{
    const float* x  = (const float*)d_in[0];
    const float* Wq = (const float*)d_in[1];
    const float* Wk = (const float*)d_in[2];
    const float* Wv = (const float*)d_in[3];
    float* out = (float*)d_out;

    qkv_kernel<<<256, 128>>>(x, Wq, Wk, Wv);   // 16384 tokens / 64 per CTA
    attn_kernel<<<640, 128>>>();               // split-K jobs, heavy first
    combine_kernel<<<256, 64>>>(out);          // merge + normalize
}

// round 8
// speedup vs baseline: 3.3952x; 1.1244x over previous
#include <cuda_runtime.h>

#define NB 8
#define NT 2048
#define NE 128
#define NH 16

// Q/K/V scratch + split-K partials (allocation-free: __device__ globals)
__device__ float g_Q[NB * NT * NH];
__device__ float g_K[NB * NT * NH];
__device__ float g_V[NB * NT * NH];
// partial state per (job=(b*32+qt)*8+kc, query): l, a[16]  (fixed softmax ref)
__device__ float g_pl[8 * 32 * 8 * 64];
__device__ float g_pa[8 * 32 * 8 * 64 * 16];

typedef unsigned long long u64;

#define MREF 12.0f   // fixed log2-domain softmax reference (|s| << 12 + 80 safe)

__device__ __forceinline__ float ex2f(float x) {
    float y;
    asm("ex2.approx.ftz.f32 %0, %1;" : "=f"(y) : "f"(x));
    return y;
}
// Blackwell packed fp32x2 (2x fp32 FMA throughput; ptxas never auto-fuses)
__device__ __forceinline__ u64 fma2(u64 a, u64 b, u64 c) {
    u64 d; asm("fma.rn.f32x2 %0, %1, %2, %3;" : "=l"(d) : "l"(a), "l"(b), "l"(c)); return d;
}
__device__ __forceinline__ u64 mul2(u64 a, u64 b) {
    u64 d; asm("mul.rn.f32x2 %0, %1, %2;" : "=l"(d) : "l"(a), "l"(b)); return d;
}
__device__ __forceinline__ u64 add2(u64 a, u64 b) {
    u64 d; asm("add.rn.f32x2 %0, %1, %2;" : "=l"(d) : "l"(a), "l"(b)); return d;
}
__device__ __forceinline__ u64 pack2(float lo, float hi) {
    u64 r; asm("mov.b64 %0, {%1,%2};" : "=l"(r) : "f"(lo), "f"(hi)); return r;
}
__device__ __forceinline__ void unpack2(u64 v, float& lo, float& hi) {
    asm("mov.b64 {%0,%1}, %2;" : "=f"(lo), "=f"(hi) : "l"(v));
}

// ---------------------------------------------------------------------------
// Kernel 1: fused QKV projection. 32 tokens/CTA (grid 512), G=2 tokens/thread.
// og = tid>>4 (8 groups x 6 cols; half-warp uniform -> W LDS broadcast N<=2),
// tg = tid&15 owns tokens tg, tg+16. Full e in one smem tile.
// ---------------------------------------------------------------------------
__global__ __launch_bounds__(128, 4) void qkv_kernel(
    const float* __restrict__ x,
    const float* __restrict__ Wq,
    const float* __restrict__ Wk,
    const float* __restrict__ Wv)
{
    __shared__ float4 sX[32 * 33];                 // 32 tokens x 32 f4, pad 33
    __shared__ __align__(16) float sWf[128 * 52];  // 128 e-rows x 48 (+4 pad)
    const int tid  = threadIdx.x;
    const int tok0 = blockIdx.x * 32;

    // x tile: 1024 float4, coalesced
    const float4* xg = reinterpret_cast<const float4*>(x) + (size_t)tok0 * 32;
#pragma unroll
    for (int i = 0; i < 8; i++) {
        int idx = i * 128 + tid;
        sX[(idx >> 5) * 33 + (idx & 31)] = xg[idx];
    }
    // W: 1536 float4 into padded rows (row stride 52 floats = 13 f4, 16B-aligned)
    const float4* wq4 = reinterpret_cast<const float4*>(Wq);
    const float4* wk4 = reinterpret_cast<const float4*>(Wk);
    const float4* wv4 = reinterpret_cast<const float4*>(Wv);
#pragma unroll
    for (int i = 0; i < 12; i++) {
        int idx = i * 128 + tid;
        int e = idx / 12, c4 = idx % 12;
        float4 w = (c4 < 4) ? wq4[e * 4 + c4]
                 : (c4 < 8) ? wk4[e * 4 + (c4 - 4)]
                            : wv4[e * 4 + (c4 - 8)];
        *reinterpret_cast<float4*>(&sWf[e * 52 + c4 * 4]) = w;
    }
    __syncthreads();

    const int og = tid >> 4;     // 0..7, 6 cols each (half-warp uniform)
    const int tg = tid & 15;     // token slot: owns tg and tg+16
    u64 acc[6] = {0ull, 0ull, 0ull, 0ull, 0ull, 0ull};

#pragma unroll 4
    for (int e4 = 0; e4 < 32; e4++) {
        float4 xv0 = sX[tg * 33 + e4];
        float4 xv1 = sX[(tg + 16) * 33 + e4];
        float xs0[4] = {xv0.x, xv0.y, xv0.z, xv0.w};
        float xs1[4] = {xv1.x, xv1.y, xv1.z, xv1.w};
#pragma unroll
        for (int u = 0; u < 4; u++) {
            const u64* wp = reinterpret_cast<const u64*>(
                &sWf[(e4 * 4 + u) * 52 + og * 6]);   // 8B-aligned (og*24B)
            u64 w0 = wp[0], w1 = wp[1], w2 = wp[2];  // broadcast LDS.64
            u64 x0 = pack2(xs0[u], xs0[u]);
            u64 x1 = pack2(xs1[u], xs1[u]);
            acc[0] = fma2(x0, w0, acc[0]);
            acc[1] = fma2(x0, w1, acc[1]);
            acc[2] = fma2(x0, w2, acc[2]);
            acc[3] = fma2(x1, w0, acc[3]);
            acc[4] = fma2(x1, w1, acc[4]);
            acc[5] = fma2(x1, w2, acc[5]);
        }
    }

    float av[12];
#pragma unroll
    for (int i = 0; i < 6; i++) unpack2(acc[i], av[2 * i], av[2 * i + 1]);

#pragma unroll
    for (int t = 0; t < 2; t++) {
        const int tok = tok0 + tg + t * 16;
        const float* avt = av + t * 6;
#pragma unroll
        for (int k = 0; k < 6; k++) {
            int c = og * 6 + k;
            float* base = (c < 16) ? g_Q : (c < 32) ? g_K : g_V;
            base[(size_t)tok * NH + (c & 15)] = avt[k];
        }
    }
}

// ---------------------------------------------------------------------------
// Kernel 2: split-K causal flash attention, FIXED-REFERENCE softmax
// (p = 2^(s-MREF): no running max, no rescale, no loop-carried chains).
// Job = (b, qt: 64-query tile, kc: 256-key chunk) -> 1152 jobs, ~2 tiles each.
// Warp = key phase (pairs {2r,2r+1} mod 8 -> broadcast LDS), lane = query slot
// (owns qt*64+lane and +32).
// ---------------------------------------------------------------------------
__device__ __forceinline__ void scores2(
    const ulonglong2* __restrict__ kp, const u64* __restrict__ q,
    float& s0a, float& s1a, float& s0b, float& s1b)
{
    ulonglong2 a0 = kp[0], a1 = kp[1], a2 = kp[2], a3 = kp[3];
    ulonglong2 b0 = kp[4], b1 = kp[5], b2 = kp[6], b3 = kp[7];
    u64 t; float lo, hi;
    t = fma2(q[0], a0.x, fma2(q[2], a1.x, fma2(q[4], a2.x, mul2(q[6],  a3.x))));
    t = add2(t, fma2(q[1], a0.y, fma2(q[3], a1.y, fma2(q[5], a2.y, mul2(q[7],  a3.y)))));
    unpack2(t, lo, hi); s0a = lo + hi;
    t = fma2(q[8], a0.x, fma2(q[10],a1.x, fma2(q[12],a2.x, mul2(q[14], a3.x))));
    t = add2(t, fma2(q[9], a0.y, fma2(q[11],a1.y, fma2(q[13],a2.y, mul2(q[15], a3.y)))));
    unpack2(t, lo, hi); s1a = lo + hi;
    t = fma2(q[0], b0.x, fma2(q[2], b1.x, fma2(q[4], b2.x, mul2(q[6],  b3.x))));
    t = add2(t, fma2(q[1], b0.y, fma2(q[3], b1.y, fma2(q[5], b2.y, mul2(q[7],  b3.y)))));
    unpack2(t, lo, hi); s0b = lo + hi;
    t = fma2(q[8], b0.x, fma2(q[10],b1.x, fma2(q[12],b2.x, mul2(q[14], b3.x))));
    t = add2(t, fma2(q[9], b0.y, fma2(q[11],b1.y, fma2(q[13],b2.y, mul2(q[15], b3.y)))));
    unpack2(t, lo, hi); s1b = lo + hi;
}

template<bool MASKED>
__device__ __forceinline__ void updF(
    float sa, float sb, bool oka, bool okb,
    float& l, u64* __restrict__ a,
    const ulonglong2& va0, const ulonglong2& va1,
    const ulonglong2& va2, const ulonglong2& va3,
    const ulonglong2& vb0, const ulonglong2& vb1,
    const ulonglong2& vb2, const ulonglong2& vb3)
{
    float pa = ex2f(sa - MREF);
    float pb = ex2f(sb - MREF);
    if (MASKED) {                 // FSEL, no branch
        pa = oka ? pa : 0.f;
        pb = okb ? pb : 0.f;
    }
    l += pa + pb;
    u64 pap = pack2(pa, pa), pbp = pack2(pb, pb);
    a[0] = fma2(pap, va0.x, fma2(pbp, vb0.x, a[0]));
    a[1] = fma2(pap, va0.y, fma2(pbp, vb0.y, a[1]));
    a[2] = fma2(pap, va1.x, fma2(pbp, vb1.x, a[2]));
    a[3] = fma2(pap, va1.y, fma2(pbp, vb1.y, a[3]));
    a[4] = fma2(pap, va2.x, fma2(pbp, vb2.x, a[4]));
    a[5] = fma2(pap, va2.y, fma2(pbp, vb2.y, a[5]));
    a[6] = fma2(pap, va3.x, fma2(pbp, vb3.x, a[6]));
    a[7] = fma2(pap, va3.y, fma2(pbp, vb3.y, a[7]));
}

__global__ __launch_bounds__(128, 3) void attn_kernel()
{
    __shared__ float4 sbuf[1024];    // K[512] | V[512]; reused for combine
    float4* sK4 = sbuf;
    float4* sV4 = sbuf + 512;

    // job decode: groups g=7..0 (qt in [4g,4g+4), g+1 chunks per qt), heavy first
    const int bid = blockIdx.x;           // 0..1151
    const int b   = bid & 7;
    int rem = bid >> 3;                   // 0..143
    int g = 7;
    while (rem >= 4 * (g + 1)) { rem -= 4 * (g + 1); g--; }
    const int qt = 4 * g + rem / (g + 1);
    const int kc = rem % (g + 1);

    const int tid  = threadIdx.x;
    const int r    = tid >> 5;            // warp id = key-pair phase (uniform)
    const int lane = tid & 31;            // query slot
    const int qg0  = qt * 64 + lane;
    const int qg1  = qg0 + 32;
    const int ks0  = kc << 8;             // 256-key chunk base
    const int ttot = (qt >> 1) + 1;       // total 128-key tiles for this qt
    const int ntiles = min(2, ttot - 2 * kc);

    const float SC = 0.25f * 1.44269504088896340736f;  // H^-0.5 * log2(e)
    u64 q[16];
    {
        const float4* qp0 = reinterpret_cast<const float4*>(g_Q + ((size_t)b * NT + qg0) * NH);
        const float4* qp1 = reinterpret_cast<const float4*>(g_Q + ((size_t)b * NT + qg1) * NH);
#pragma unroll
        for (int i = 0; i < 4; i++) {
            float4 t0 = qp0[i], t1 = qp1[i];
            q[2*i]     = pack2(t0.x * SC, t0.y * SC);
            q[2*i+1]   = pack2(t0.z * SC, t0.w * SC);
            q[8+2*i]   = pack2(t1.x * SC, t1.y * SC);
            q[8+2*i+1] = pack2(t1.z * SC, t1.w * SC);
        }
    }

    float l0 = 0.f, l1 = 0.f;
    u64 a[16];
#pragma unroll
    for (int i = 0; i < 16; i++) a[i] = 0ull;

    const float4* Kg = reinterpret_cast<const float4*>(g_K + (size_t)b * NT * NH);
    const float4* Vg = reinterpret_cast<const float4*>(g_V + (size_t)b * NT * NH);
    const ulonglong2* sK2 = reinterpret_cast<const ulonglong2*>(sK4);
    const ulonglong2* sV2 = reinterpret_cast<const ulonglong2*>(sV4);

    for (int kt = 0; kt < ntiles; kt++) {
        const int kb = ks0 + (kt << 7);   // tile key base
#pragma unroll
        for (int i = 0; i < 4; i++) {
            int idx = i * 128 + tid;
            sK4[idx] = Kg[(size_t)kb * 4 + idx];
            sV4[idx] = Vg[(size_t)kb * 4 + idx];
        }
        __syncthreads();

        if (kb + 127 <= qt * 64) {
            // full tile: 16 key-pairs per warp, no masks
#pragma unroll 4
            for (int jj = 0; jj < 16; jj++) {
                int j0 = 8 * jj + 2 * r;          // warp-uniform
                float s0a, s1a, s0b, s1b;
                scores2(sK2 + j0 * 4, q, s0a, s1a, s0b, s1b);
                const ulonglong2* vp = sV2 + j0 * 4;
                ulonglong2 va0 = vp[0], va1 = vp[1], va2 = vp[2], va3 = vp[3];
                ulonglong2 vb0 = vp[4], vb1 = vp[5], vb2 = vp[6], vb3 = vp[7];
                updF<false>(s0a, s0b, true, true, l0, a,
                            va0, va1, va2, va3, vb0, vb1, vb2, vb3);
                updF<false>(s1a, s1b, true, true, l1, a + 8,
                            va0, va1, va2, va3, vb0, vb1, vb2, vb3);
            }
        } else {
            // diagonal tile: per-lane causal masks via FSEL (p zeroed)
            const int jmax = min(127, qt * 64 + 63 - kb);
            for (int j0 = 2 * r; j0 <= jmax; j0 += 8) {
                float s0a, s1a, s0b, s1b;
                scores2(sK2 + j0 * 4, q, s0a, s1a, s0b, s1b);
                const ulonglong2* vp = sV2 + j0 * 4;
                ulonglong2 va0 = vp[0], va1 = vp[1], va2 = vp[2], va3 = vp[3];
                ulonglong2 vb0 = vp[4], vb1 = vp[5], vb2 = vp[6], vb3 = vp[7];
                int kja = kb + j0, kjb = kja + 1;
                updF<true>(s0a, s0b, kja <= qg0, kjb <= qg0, l0, a,
                           va0, va1, va2, va3, vb0, vb1, vb2, vb3);
                updF<true>(s1a, s1b, kja <= qg1, kjb <= qg1, l1, a + 8,
                           va0, va1, va2, va3, vb0, vb1, vb2, vb3);
            }
        }
        __syncthreads();
    }

    // cross-warp combine (fixed reference -> plain sums): warps 1..3 stage,
    // warp 0 adds. stride-5 ulonglong2 layout, conflict-free.
    ulonglong2* cb = reinterpret_cast<ulonglong2*>(sbuf);
    if (r > 0) {
#pragma unroll
        for (int qi = 0; qi < 2; qi++) {
            int base = ((r - 1) * 2 + qi) * 160 + lane * 5;
            const u64* aq = a + qi * 8;
            cb[base + 0] = make_ulonglong2(aq[0], aq[1]);
            cb[base + 1] = make_ulonglong2(aq[2], aq[3]);
            cb[base + 2] = make_ulonglong2(aq[4], aq[5]);
            cb[base + 3] = make_ulonglong2(aq[6], aq[7]);
            cb[base + 4] = make_ulonglong2(pack2(qi == 0 ? l0 : l1, 0.f), 0ull);
        }
    }
    __syncthreads();

    if (r == 0) {
#pragma unroll
        for (int w = 1; w < 4; w++) {
#pragma unroll
            for (int qi = 0; qi < 2; qi++) {
                int base = ((w - 1) * 2 + qi) * 160 + lane * 5;
                float lw, dummy;
                unpack2(cb[base + 4].x, lw, dummy);
                if (qi == 0) l0 += lw; else l1 += lw;
                u64* aq = a + qi * 8;
#pragma unroll
                for (int i = 0; i < 4; i++) {
                    ulonglong2 t = cb[base + i];
                    aq[2*i]   = add2(aq[2*i],   t.x);
                    aq[2*i+1] = add2(aq[2*i+1], t.y);
                }
            }
        }
        // emit split-K partial (shared fixed reference -> just l and a)
        const int jid = ((b * 32 + qt) << 3) + kc;
        g_pl[jid * 64 + lane]      = l0;
        g_pl[jid * 64 + lane + 32] = l1;
        float oc[32];
#pragma unroll
        for (int i = 0; i < 8; i++) {
            unpack2(a[i],     oc[2*i],    oc[2*i+1]);
            unpack2(a[i + 8], oc[16+2*i], oc[16+2*i+1]);
        }
        float4* p0 = reinterpret_cast<float4*>(&g_pa[(size_t)(jid * 64 + lane) * 16]);
        float4* p1 = reinterpret_cast<float4*>(&g_pa[(size_t)(jid * 64 + lane + 32) * 16]);
#pragma unroll
        for (int i = 0; i < 4; i++) {
            p0[i] = make_float4(oc[4*i],    oc[4*i+1],    oc[4*i+2],    oc[4*i+3]);
            p1[i] = make_float4(oc[16+4*i], oc[16+4*i+1], oc[16+4*i+2], oc[16+4*i+3]);
        }
    }
}

// ---------------------------------------------------------------------------
// Kernel 3: sum <=8 split-K partials per query (shared reference) + normalize.
// ---------------------------------------------------------------------------
__global__ __launch_bounds__(64, 8) void combine_kernel(float* __restrict__ out)
{
    const int bq = blockIdx.x;            // 0..255
    const int b  = bq >> 5, qt = bq & 31;
    const int ql = threadIdx.x;           // 0..63
    const int nc = (qt >> 2) + 1;
    const int base = (b * 32 + qt) << 3;

    float L = 0.f;
    float acc[16];
#pragma unroll
    for (int i = 0; i < 16; i++) acc[i] = 0.f;

    for (int c = 0; c < nc; c++) {
        L += g_pl[(base + c) * 64 + ql];
        const float4* pa = reinterpret_cast<const float4*>(
            &g_pa[(size_t)((base + c) * 64 + ql) * 16]);
#pragma unroll
        for (int i = 0; i < 4; i++) {
            float4 v = pa[i];
            acc[4*i+0] += v.x;
            acc[4*i+1] += v.y;
            acc[4*i+2] += v.z;
            acc[4*i+3] += v.w;
        }
    }
    float inv = 1.0f / L;
    float4* op = reinterpret_cast<float4*>(out + ((size_t)b * NT + qt * 64 + ql) * NH);
#pragma unroll
    for (int i = 0; i < 4; i++)
        op[i] = make_float4(acc[4*i] * inv, acc[4*i+1] * inv,
                            acc[4*i+2] * inv, acc[4*i+3] * inv);
}

extern "C" void kernel_launch(void* const* d_in, const int* in_sizes, int n_in,
                              void* d_out, int out_size)
{
    const float* x  = (const float*)d_in[0];
    const float* Wq = (const float*)d_in[1];
    const float* Wk = (const float*)d_in[2];
    const float* Wv = (const float*)d_in[3];
    float* out = (float*)d_out;

    qkv_kernel<<<512, 128>>>(x, Wq, Wk, Wv);   // 16384 tokens / 32 per CTA
    attn_kernel<<<1152, 128>>>();              // 256-key split-K jobs
    combine_kernel<<<256, 64>>>(out);          // sum + normalize
}